// round 6
// baseline (speedup 1.0000x reference)
#include <cuda_runtime.h>
#include <cuda_bf16.h>
#include <math.h>
#include <stdint.h>

#define BATCH   2
#define SEQ     2048
#define DMODEL  1024
#define NHEADS  16
#define HDIM    64
#define WIN     64
#define MTOT    (BATCH*SEQ)   // 4096
#define WSZ     (DMODEL*DMODEL)

// ---------------- scratch (static device globals) ----------------
__device__ __nv_bfloat16 g_xh[MTOT*DMODEL];
__device__ __nv_bfloat16 g_xl[MTOT*DMODEL];
__device__ __nv_bfloat16 g_wh[4*WSZ];   // transposed [n][k], bf16 hi
__device__ __nv_bfloat16 g_wl[4*WSZ];   // transposed [n][k], bf16 lo
__device__ __nv_bfloat16 g_qh[MTOT*DMODEL];
__device__ __nv_bfloat16 g_ql[MTOT*DMODEL];
__device__ __nv_bfloat16 g_kh[MTOT*DMODEL];
__device__ __nv_bfloat16 g_kl[MTOT*DMODEL];
__device__ __nv_bfloat16 g_vh[MTOT*DMODEL];
__device__ __nv_bfloat16 g_vl[MTOT*DMODEL];
__device__ __nv_bfloat16 g_ah[MTOT*DMODEL];  // attention out, bf16 hi
__device__ __nv_bfloat16 g_al[MTOT*DMODEL];  // attention out, bf16 lo

// ---------------- PTX helpers (non-'a' features only) ----------------
__device__ __forceinline__ uint32_t smem_u32(const void* p) {
    uint32_t a;
    asm("{ .reg .u64 t; cvta.to.shared.u64 t, %1; cvt.u32.u64 %0, t; }" : "=r"(a) : "l"(p));
    return a;
}
__device__ __forceinline__ void cp_async16(uint32_t s, const void* g) {
    asm volatile("cp.async.cg.shared.global [%0], [%1], 16;" :: "r"(s), "l"(g));
}
__device__ __forceinline__ void cp_async16z(uint32_t s, const void* g, uint32_t srcsz) {
    asm volatile("cp.async.cg.shared.global [%0], [%1], 16, %2;" :: "r"(s), "l"(g), "r"(srcsz));
}
#define CP_COMMIT() asm volatile("cp.async.commit_group;" ::: "memory")
#define CP_WAIT(n)  asm volatile("cp.async.wait_group %0;" :: "n"(n) : "memory")

__device__ __forceinline__ void ldsm_x4(uint32_t* r, uint32_t a) {
    asm volatile("ldmatrix.sync.aligned.m8n8.x4.shared.b16 {%0,%1,%2,%3}, [%4];"
        : "=r"(r[0]), "=r"(r[1]), "=r"(r[2]), "=r"(r[3]) : "r"(a));
}
__device__ __forceinline__ void ldsm_x2t(uint32_t* r, uint32_t a) {
    asm volatile("ldmatrix.sync.aligned.m8n8.x2.trans.shared.b16 {%0,%1}, [%2];"
        : "=r"(r[0]), "=r"(r[1]) : "r"(a));
}
__device__ __forceinline__ void mma_bf16(float* d, const uint32_t* a, const uint32_t* b) {
    asm volatile(
        "mma.sync.aligned.m16n8k16.row.col.f32.bf16.bf16.f32 "
        "{%0,%1,%2,%3}, {%4,%5,%6,%7}, {%8,%9}, {%0,%1,%2,%3};"
        : "+f"(d[0]), "+f"(d[1]), "+f"(d[2]), "+f"(d[3])
        : "r"(a[0]), "r"(a[1]), "r"(a[2]), "r"(a[3]), "r"(b[0]), "r"(b[1]));
}

__device__ __forceinline__ uint32_t pack_bf2(float x, float y) {
    __nv_bfloat162 h;
    h.x = __float2bfloat16(x); h.y = __float2bfloat16(y);
    return *(uint32_t*)&h;
}

// ============================================================
// Conversion kernels
// ============================================================
__global__ __launch_bounds__(256) void convert_x_kernel(const float* __restrict__ x)
{
    size_t off = (size_t)blockIdx.x * DMODEL + threadIdx.x * 4;
    float4 v = *(const float4*)(x + off);
    __nv_bfloat162 h01, h23, l01, l23;
    h01.x = __float2bfloat16(v.x); l01.x = __float2bfloat16(v.x - __bfloat162float(h01.x));
    h01.y = __float2bfloat16(v.y); l01.y = __float2bfloat16(v.y - __bfloat162float(h01.y));
    h23.x = __float2bfloat16(v.z); l23.x = __float2bfloat16(v.z - __bfloat162float(h23.x));
    h23.y = __float2bfloat16(v.w); l23.y = __float2bfloat16(v.w - __bfloat162float(h23.y));
    *(__nv_bfloat162*)(g_xh + off) = h01; *(__nv_bfloat162*)(g_xh + off + 2) = h23;
    *(__nv_bfloat162*)(g_xl + off) = l01; *(__nv_bfloat162*)(g_xl + off + 2) = l23;
}

// transpose W[k][n] -> Wt[n][k], split hi/lo. block (32,8), tile 32x32
__global__ __launch_bounds__(256) void transpose_w_kernel(
    const float* __restrict__ Wq, const float* __restrict__ Wk,
    const float* __restrict__ Wv, const float* __restrict__ Wo)
{
    __shared__ float tile[32][33];
    int z = blockIdx.z;
    const float* W = (z == 0) ? Wq : (z == 1) ? Wk : (z == 2) ? Wv : Wo;
    __nv_bfloat16* Th = g_wh + (size_t)z * WSZ;
    __nv_bfloat16* Tl = g_wl + (size_t)z * WSZ;
    int kb = blockIdx.y * 32, nb = blockIdx.x * 32;
    int tx = threadIdx.x, ty = threadIdx.y;
#pragma unroll
    for (int i = 0; i < 4; i++)
        tile[ty + 8 * i][tx] = W[(size_t)(kb + ty + 8 * i) * DMODEL + nb + tx];
    __syncthreads();
#pragma unroll
    for (int i = 0; i < 4; i++) {
        float v = tile[tx][ty + 8 * i];
        __nv_bfloat16 h = __float2bfloat16(v);
        __nv_bfloat16 l = __float2bfloat16(v - __bfloat162float(h));
        size_t o = (size_t)(nb + ty + 8 * i) * DMODEL + kb + tx;
        Th[o] = h; Tl[o] = l;
    }
}

// ============================================================
// Split-bf16 HMMA GEMM (R4-proven layout, 3-stage pipeline)
// CTA tile 128x128, BK=32, 8 warps, warp tile 64x32.
// A/B smem pitch 80 B; W transposed [n][k].
// ============================================================
#define BK       32
#define PITCHB   80                    // bytes per SMEM row
#define MAT_B    (128*PITCHB)          // 10240 B
#define STAGE_B2 (4*MAT_B)             // 40960 B per stage
#define NSTAGE   3
#define GEMM_SMEM (NSTAGE*STAGE_B2)    // 122880 B
#define ROW64B   (64*PITCHB)

__global__ __launch_bounds__(256) void hmma_gemm_kernel(
    int mode, const float* __restrict__ b0, const float* __restrict__ b1,
    const float* __restrict__ b2, float* __restrict__ outp)
{
    extern __shared__ char sm[];
    const uint32_t sbase = smem_u32(sm);

    const int tid  = threadIdx.x;
    const int lane = tid & 31;
    const int wid  = tid >> 5;
    const int wm   = wid >> 2;
    const int wn   = wid & 3;
    const int m0   = blockIdx.y * 128;
    const int n0   = blockIdx.x * 128;
    const int z    = blockIdx.z;

    const __nv_bfloat16 *Ah, *Al, *Bh, *Bl;
    const float* bias;
    if (mode == 0) {
        Ah = g_xh; Al = g_xl;
        Bh = g_wh + (size_t)z * WSZ; Bl = g_wl + (size_t)z * WSZ;
        bias = (z == 0) ? b0 : (z == 1) ? b1 : b2;
    } else {
        Ah = g_ah; Al = g_al;
        Bh = g_wh + 3ull * WSZ; Bl = g_wl + 3ull * WSZ;
        bias = b0;
    }

    const int rowA = tid >> 2;
    const int seg  = tid & 3;
    const uint32_t s0 = (uint32_t)rowA * PITCHB + (uint32_t)seg * 16;
    const __nv_bfloat16* pAh = Ah + (size_t)(m0 + rowA) * DMODEL + seg * 8;
    const __nv_bfloat16* pAl = Al + (size_t)(m0 + rowA) * DMODEL + seg * 8;
    const __nv_bfloat16* pBh = Bh + (size_t)(n0 + rowA) * DMODEL + seg * 8;
    const __nv_bfloat16* pBl = Bl + (size_t)(n0 + rowA) * DMODEL + seg * 8;

#define PREFETCH(stage, cc) do {                                             \
    const int _k0 = (cc) * BK;                                               \
    const uint32_t _sb = sbase + (uint32_t)(stage) * STAGE_B2 + s0;          \
    cp_async16(_sb,                      pAh + _k0);                         \
    cp_async16(_sb + ROW64B,             pAh + 64 * DMODEL + _k0);           \
    cp_async16(_sb + MAT_B,              pAl + _k0);                         \
    cp_async16(_sb + MAT_B + ROW64B,     pAl + 64 * DMODEL + _k0);           \
    cp_async16(_sb + 2 * MAT_B,          pBh + _k0);                         \
    cp_async16(_sb + 2 * MAT_B + ROW64B, pBh + 64 * DMODEL + _k0);           \
    cp_async16(_sb + 3 * MAT_B,          pBl + _k0);                         \
    cp_async16(_sb + 3 * MAT_B + ROW64B, pBl + 64 * DMODEL + _k0);           \
} while (0)

    float acc[4][4][4];
#pragma unroll
    for (int i = 0; i < 4; i++)
#pragma unroll
        for (int j = 0; j < 4; j++)
#pragma unroll
            for (int e = 0; e < 4; e++) acc[i][j][e] = 0.f;

    const int arow_l = ((lane >> 3) & 1) * 8 + (lane & 7);
    const int akoff  = (lane >> 4) * 8;
    // B x4 fragment lane mapping: rows +(lane>>4)*8, k-halves by ((lane>>3)&1)
    const int brow4  = (lane & 7) + ((lane >> 4) << 3);
    const int bko4   = ((lane >> 3) & 1) * 16;      // bytes

    PREFETCH(0, 0); CP_COMMIT();
    PREFETCH(1, 1); CP_COMMIT();

    const int NCHUNK = DMODEL / BK;   // 32
    int scur = 0, spre = 2;
    for (int c = 0; c < NCHUNK; c++) {
        if (c + 2 < NCHUNK) { PREFETCH(spre, c + 2); CP_COMMIT(); CP_WAIT(2); }
        else if (c + 1 < NCHUNK) { CP_WAIT(1); }
        else { CP_WAIT(0); }
        __syncthreads();

        const uint32_t stb = sbase + (uint32_t)scur * STAGE_B2;
#pragma unroll
        for (int ks = 0; ks < 2; ks++) {
            uint32_t ah[4][4], al[4][4], bh4[2][4], bl4[2][4];
#pragma unroll
            for (int mt = 0; mt < 4; mt++) {
                uint32_t ad = stb + (uint32_t)(wm * 64 + mt * 16 + arow_l) * PITCHB
                                  + (uint32_t)(ks * 16 + akoff) * 2;
                ldsm_x4(ah[mt], ad);
                ldsm_x4(al[mt], ad + MAT_B);
            }
#pragma unroll
            for (int np = 0; np < 2; np++) {
                uint32_t bd = stb + 2 * MAT_B
                                  + (uint32_t)(wn * 32 + np * 16 + brow4) * PITCHB
                                  + (uint32_t)(ks * 32 + bko4);
                ldsm_x4(bh4[np], bd);
                ldsm_x4(bl4[np], bd + MAT_B);
            }
#pragma unroll
            for (int mt = 0; mt < 4; mt++)
#pragma unroll
                for (int nt = 0; nt < 4; nt++) {
                    uint32_t bh[2] = { bh4[nt >> 1][(nt & 1) * 2 + 0], bh4[nt >> 1][(nt & 1) * 2 + 1] };
                    uint32_t bl[2] = { bl4[nt >> 1][(nt & 1) * 2 + 0], bl4[nt >> 1][(nt & 1) * 2 + 1] };
                    mma_bf16(acc[mt][nt], ah[mt], bh);
                    mma_bf16(acc[mt][nt], ah[mt], bl);
                    mma_bf16(acc[mt][nt], al[mt], bh);
                }
        }
        __syncthreads();
        scur = (scur == 2) ? 0 : scur + 1;
        spre = (spre == 2) ? 0 : spre + 1;
    }

    const int g     = lane >> 2;
    const int cpair = (lane & 3) * 2;
    if (mode == 0) {
        __nv_bfloat16* Ch = (z == 0) ? g_qh : (z == 1) ? g_kh : g_vh;
        __nv_bfloat16* Cl = (z == 0) ? g_ql : (z == 1) ? g_kl : g_vl;
#pragma unroll
        for (int mt = 0; mt < 4; mt++) {
            int row0 = m0 + wm * 64 + mt * 16 + g;
#pragma unroll
            for (int nt = 0; nt < 4; nt++) {
                int col = n0 + wn * 32 + nt * 8 + cpair;
                float bx = bias[col], by = bias[col + 1];
#pragma unroll
                for (int rr = 0; rr < 2; rr++) {
                    float o0 = acc[mt][nt][rr * 2 + 0] + bx;
                    float o1 = acc[mt][nt][rr * 2 + 1] + by;
                    __nv_bfloat162 h2, l2;
                    h2.x = __float2bfloat16(o0); l2.x = __float2bfloat16(o0 - __bfloat162float(h2.x));
                    h2.y = __float2bfloat16(o1); l2.y = __float2bfloat16(o1 - __bfloat162float(h2.y));
                    size_t off = (size_t)(row0 + rr * 8) * DMODEL + col;
                    *(__nv_bfloat162*)(Ch + off) = h2;
                    *(__nv_bfloat162*)(Cl + off) = l2;
                }
            }
        }
    } else {
        float* C = outp;
#pragma unroll
        for (int mt = 0; mt < 4; mt++) {
            int row0 = m0 + wm * 64 + mt * 16 + g;
#pragma unroll
            for (int nt = 0; nt < 4; nt++) {
                int col = n0 + wn * 32 + nt * 8 + cpair;
                float bx = bias[col], by = bias[col + 1];
                *(float2*)(C + (size_t)row0 * DMODEL + col) =
                    make_float2(acc[mt][nt][0] + bx, acc[mt][nt][1] + by);
                *(float2*)(C + (size_t)(row0 + 8) * DMODEL + col) =
                    make_float2(acc[mt][nt][2] + bx, acc[mt][nt][3] + by);
            }
        }
    }
#undef PREFETCH
}

// ============================================================
// Banded flash-attention with mma.sync (split bf16 hi/lo)
// CTA = (128 queries, head, batch); 8 warps; warp = 16 query rows.
// K/V band = 256 rows; per-warp valid band = 144 keys = 18 n-tiles.
// ============================================================
#define APITCHB  144
#define A_QH     0
#define A_QL     18432              // 128*144
#define A_KH     36864
#define A_KL     73728              // +256*144
#define A_VH     110592
#define A_VL     147456
#define ATTN_SMEM 184320

__global__ __launch_bounds__(256) void attn_mma_kernel()
{
    extern __shared__ char sm[];
    const uint32_t sb = smem_u32(sm);

    const int tid  = threadIdx.x;
    const int lane = tid & 31;
    const int w    = tid >> 5;          // 0..7
    const int b    = blockIdx.z;
    const int h    = blockIdx.y;
    const int q0   = blockIdx.x * 128;
    const int kbase = q0 - WIN;
    const size_t tok0 = (size_t)b * SEQ;
    const int coff = h * HDIM;

    // ---- group 0: Q (128 rows) + K (256 rows); group 1: V (256 rows) ----
#pragma unroll
    for (int i = 0; i < 4; i++) {
        int task = tid + i * 256;          // 1024 tasks
        int row = task >> 3, seg = task & 7;
        uint32_t d = sb + A_QH + (uint32_t)row * APITCHB + (uint32_t)seg * 16;
        size_t goff = (tok0 + q0 + row) * DMODEL + coff + seg * 8;
        cp_async16(d,                 g_qh + goff);
        cp_async16(d + (A_QL - A_QH), g_ql + goff);
    }
#pragma unroll
    for (int i = 0; i < 8; i++) {
        int task = tid + i * 256;          // 2048 tasks
        int row = task >> 3, seg = task & 7;
        int kg = kbase + row;
        int kgc = min(max(kg, 0), SEQ - 1);
        uint32_t sz = (kg >= 0 && kg < SEQ) ? 16u : 0u;
        uint32_t d = sb + A_KH + (uint32_t)row * APITCHB + (uint32_t)seg * 16;
        size_t goff = (tok0 + kgc) * DMODEL + coff + seg * 8;
        cp_async16z(d,                 g_kh + goff, sz);
        cp_async16z(d + (A_KL - A_KH), g_kl + goff, sz);
    }
    CP_COMMIT();
#pragma unroll
    for (int i = 0; i < 8; i++) {
        int task = tid + i * 256;
        int row = task >> 3, seg = task & 7;
        int kg = kbase + row;
        int kgc = min(max(kg, 0), SEQ - 1);
        uint32_t sz = (kg >= 0 && kg < SEQ) ? 16u : 0u;
        uint32_t d = sb + A_VH + (uint32_t)row * APITCHB + (uint32_t)seg * 16;
        size_t goff = (tok0 + kgc) * DMODEL + coff + seg * 8;
        cp_async16z(d,                 g_vh + goff, sz);
        cp_async16z(d + (A_VL - A_VH), g_vl + goff, sz);
    }
    CP_COMMIT();

    CP_WAIT(1);
    __syncthreads();

    // ---- Q fragments ----
    const int arow = w * 16 + ((lane >> 3) & 1) * 8 + (lane & 7);
    const int akoff = (lane >> 4) * 8;
    uint32_t qfh[4][4], qfl[4][4];
#pragma unroll
    for (int kc = 0; kc < 4; kc++) {
        uint32_t ad = sb + A_QH + (uint32_t)arow * APITCHB + (uint32_t)(kc * 16 + akoff) * 2;
        ldsm_x4(qfh[kc], ad);
        ldsm_x4(qfl[kc], ad + (A_QL - A_QH));
    }

    // ---- QK: S[16][144], 18 n-tiles processed as 9 pairs via ldsm_x4 ----
    float s[18][4];
#pragma unroll
    for (int t = 0; t < 18; t++)
#pragma unroll
        for (int e = 0; e < 4; e++) s[t][e] = 0.f;

    const int krow4 = (lane & 7) + ((lane >> 4) << 3);
    const int kko4  = ((lane >> 3) & 1) * 16;       // bytes
#pragma unroll
    for (int u = 0; u < 9; u++) {
        int ntb = 2 * w + 2 * u;
        uint32_t kb_addr = sb + A_KH + (uint32_t)(ntb * 8 + krow4) * APITCHB + (uint32_t)kko4;
#pragma unroll
        for (int kc = 0; kc < 4; kc++) {
            uint32_t kh4[4], kl4[4];
            uint32_t ka = kb_addr + (uint32_t)kc * 32;
            ldsm_x4(kh4, ka);
            ldsm_x4(kl4, ka + (A_KL - A_KH));
            uint32_t bh0[2] = { kh4[0], kh4[1] }, bh1[2] = { kh4[2], kh4[3] };
            uint32_t bl0[2] = { kl4[0], kl4[1] }, bl1[2] = { kl4[2], kl4[3] };
            mma_bf16(s[2 * u],     qfh[kc], bh0);
            mma_bf16(s[2 * u],     qfh[kc], bl0);
            mma_bf16(s[2 * u],     qfl[kc], bh0);
            mma_bf16(s[2 * u + 1], qfh[kc], bh1);
            mma_bf16(s[2 * u + 1], qfh[kc], bl1);
            mma_bf16(s[2 * u + 1], qfl[kc], bh1);
        }
    }

    // ---- mask + softmax ----
    const int g  = lane >> 2;
    const int c2 = (lane & 3) * 2;
    const int qg0 = q0 + w * 16 + g;
    const int qg1 = qg0 + 8;
    const float scale = 0.125f;

    float m0 = -1e30f, m1 = -1e30f;
#pragma unroll
    for (int t = 0; t < 18; t++) {
        int j0 = (2 * w + t) * 8 + c2;
        int kg0 = kbase + j0, kg1 = kg0 + 1;
        bool in0 = (kg0 >= 0) && (kg0 < SEQ);
        bool in1 = (kg1 >= 0) && (kg1 < SEQ);
        int d00 = kg0 - qg0, d10 = kg1 - qg0, d01 = kg0 - qg1, d11 = kg1 - qg1;
        s[t][0] = (in0 && d00 <= WIN && d00 >= -WIN) ? s[t][0] * scale : -1e30f;
        s[t][1] = (in1 && d10 <= WIN && d10 >= -WIN) ? s[t][1] * scale : -1e30f;
        s[t][2] = (in0 && d01 <= WIN && d01 >= -WIN) ? s[t][2] * scale : -1e30f;
        s[t][3] = (in1 && d11 <= WIN && d11 >= -WIN) ? s[t][3] * scale : -1e30f;
        m0 = fmaxf(m0, fmaxf(s[t][0], s[t][1]));
        m1 = fmaxf(m1, fmaxf(s[t][2], s[t][3]));
    }
    m0 = fmaxf(m0, __shfl_xor_sync(0xffffffffu, m0, 1));
    m0 = fmaxf(m0, __shfl_xor_sync(0xffffffffu, m0, 2));
    m1 = fmaxf(m1, __shfl_xor_sync(0xffffffffu, m1, 1));
    m1 = fmaxf(m1, __shfl_xor_sync(0xffffffffu, m1, 2));

    float r0 = 0.f, r1 = 0.f;
#pragma unroll
    for (int t = 0; t < 18; t++) {
        s[t][0] = __expf(s[t][0] - m0);
        s[t][1] = __expf(s[t][1] - m0);
        s[t][2] = __expf(s[t][2] - m1);
        s[t][3] = __expf(s[t][3] - m1);
        r0 += s[t][0] + s[t][1];
        r1 += s[t][2] + s[t][3];
    }
    r0 += __shfl_xor_sync(0xffffffffu, r0, 1);
    r0 += __shfl_xor_sync(0xffffffffu, r0, 2);
    r1 += __shfl_xor_sync(0xffffffffu, r1, 1);
    r1 += __shfl_xor_sync(0xffffffffu, r1, 2);
    float inv0 = 1.f / r0, inv1 = 1.f / r1;

    uint32_t ph01[18], ph23[18], pl01[18], pl23[18];
#pragma unroll
    for (int t = 0; t < 18; t++) {
        float p0 = s[t][0] * inv0, p1 = s[t][1] * inv0;
        float p2 = s[t][2] * inv1, p3 = s[t][3] * inv1;
        __nv_bfloat162 h2;
        h2.x = __float2bfloat16(p0); h2.y = __float2bfloat16(p1);
        ph01[t] = *(uint32_t*)&h2;
        pl01[t] = pack_bf2(p0 - __bfloat162float(h2.x), p1 - __bfloat162float(h2.y));
        h2.x = __float2bfloat16(p2); h2.y = __float2bfloat16(p3);
        ph23[t] = *(uint32_t*)&h2;
        pl23[t] = pack_bf2(p2 - __bfloat162float(h2.x), p3 - __bfloat162float(h2.y));
    }

    CP_WAIT(0);
    __syncthreads();

    // ---- PV: out[16][64] ----
    float o[8][4];
#pragma unroll
    for (int nt = 0; nt < 8; nt++)
#pragma unroll
        for (int e = 0; e < 4; e++) o[nt][e] = 0.f;

    const int vrow_l = ((lane >> 3) & 1) * 8 + (lane & 7);
#pragma unroll
    for (int jl = 0; jl < 9; jl++) {
        uint32_t ah[4] = { ph01[2 * jl], ph23[2 * jl], ph01[2 * jl + 1], ph23[2 * jl + 1] };
        uint32_t al[4] = { pl01[2 * jl], pl23[2 * jl], pl01[2 * jl + 1], pl23[2 * jl + 1] };
        int keyb = (w + jl) * 16;
        uint32_t va_base = sb + A_VH + (uint32_t)(keyb + vrow_l) * APITCHB;
#pragma unroll
        for (int nt = 0; nt < 8; nt++) {
            uint32_t vfh[2], vfl[2];
            uint32_t va = va_base + (uint32_t)nt * 16;
            ldsm_x2t(vfh, va);
            ldsm_x2t(vfl, va + (A_VL - A_VH));
            mma_bf16(o[nt], ah, vfh);
            mma_bf16(o[nt], ah, vfl);
            mma_bf16(o[nt], al, vfh);
        }
    }

    size_t row0 = tok0 + qg0;
    size_t row1 = tok0 + qg1;
#pragma unroll
    for (int nt = 0; nt < 8; nt++) {
        int col = coff + nt * 8 + c2;
        __nv_bfloat162 h2, l2;
        h2.x = __float2bfloat16(o[nt][0]); l2.x = __float2bfloat16(o[nt][0] - __bfloat162float(h2.x));
        h2.y = __float2bfloat16(o[nt][1]); l2.y = __float2bfloat16(o[nt][1] - __bfloat162float(h2.y));
        *(__nv_bfloat162*)(g_ah + row0 * DMODEL + col) = h2;
        *(__nv_bfloat162*)(g_al + row0 * DMODEL + col) = l2;
        h2.x = __float2bfloat16(o[nt][2]); l2.x = __float2bfloat16(o[nt][2] - __bfloat162float(h2.x));
        h2.y = __float2bfloat16(o[nt][3]); l2.y = __float2bfloat16(o[nt][3] - __bfloat162float(h2.y));
        *(__nv_bfloat162*)(g_ah + row1 * DMODEL + col) = h2;
        *(__nv_bfloat162*)(g_al + row1 * DMODEL + col) = l2;
    }
}

// ============================================================
extern "C" void kernel_launch(void* const* d_in, const int* in_sizes, int n_in,
                              void* d_out, int out_size)
{
    const float* x  = (const float*)d_in[0];
    const float* Wq = (const float*)d_in[1];
    const float* bq = (const float*)d_in[2];
    const float* Wk = (const float*)d_in[3];
    const float* bk = (const float*)d_in[4];
    const float* Wv = (const float*)d_in[5];
    const float* bv = (const float*)d_in[6];
    const float* Wo = (const float*)d_in[7];
    const float* bo = (const float*)d_in[8];
    float* out = (float*)d_out;

    cudaFuncSetAttribute(hmma_gemm_kernel, cudaFuncAttributeMaxDynamicSharedMemorySize, GEMM_SMEM);
    cudaFuncSetAttribute(attn_mma_kernel, cudaFuncAttributeMaxDynamicSharedMemorySize, ATTN_SMEM);

    convert_x_kernel<<<MTOT, 256>>>(x);
    transpose_w_kernel<<<dim3(32, 32, 4), dim3(32, 8)>>>(Wq, Wk, Wv, Wo);

    dim3 gq(DMODEL / 128, MTOT / 128, 3);
    hmma_gemm_kernel<<<gq, 256, GEMM_SMEM>>>(0, bq, bk, bv, nullptr);

    dim3 ga(SEQ / 128, NHEADS, BATCH);
    attn_mma_kernel<<<ga, 256, ATTN_SMEM>>>();

    dim3 go(DMODEL / 128, MTOT / 128, 1);
    hmma_gemm_kernel<<<go, 256, GEMM_SMEM>>>(1, bo, nullptr, nullptr, out);
}

// round 7
// speedup vs baseline: 1.1140x; 1.1140x over previous
#include <cuda_runtime.h>
#include <cuda_bf16.h>
#include <math.h>
#include <stdint.h>

#define BATCH   2
#define SEQ     2048
#define DMODEL  1024
#define NHEADS  16
#define HDIM    64
#define WIN     64
#define MTOT    (BATCH*SEQ)   // 4096
#define WSZ     (DMODEL*DMODEL)

// ---------------- scratch (static device globals) ----------------
__device__ __nv_bfloat16 g_xh[MTOT*DMODEL];
__device__ __nv_bfloat16 g_xl[MTOT*DMODEL];
__device__ __nv_bfloat16 g_wh[4*WSZ];   // transposed [n][k], bf16 hi
__device__ __nv_bfloat16 g_wl[4*WSZ];   // transposed [n][k], bf16 lo
__device__ __nv_bfloat16 g_qh[MTOT*DMODEL];
__device__ __nv_bfloat16 g_ql[MTOT*DMODEL];
__device__ __nv_bfloat16 g_kh[MTOT*DMODEL];
__device__ __nv_bfloat16 g_kl[MTOT*DMODEL];
__device__ __nv_bfloat16 g_vh[MTOT*DMODEL];
__device__ __nv_bfloat16 g_vl[MTOT*DMODEL];
__device__ __nv_bfloat16 g_ah[MTOT*DMODEL];  // attention out, bf16 hi
__device__ __nv_bfloat16 g_al[MTOT*DMODEL];  // attention out, bf16 lo

// ---------------- PTX helpers (non-'a' features only) ----------------
__device__ __forceinline__ uint32_t smem_u32(const void* p) {
    uint32_t a;
    asm("{ .reg .u64 t; cvta.to.shared.u64 t, %1; cvt.u32.u64 %0, t; }" : "=r"(a) : "l"(p));
    return a;
}
__device__ __forceinline__ void cp_async16(uint32_t s, const void* g) {
    asm volatile("cp.async.cg.shared.global [%0], [%1], 16;" :: "r"(s), "l"(g));
}
__device__ __forceinline__ void cp_async16z(uint32_t s, const void* g, uint32_t srcsz) {
    asm volatile("cp.async.cg.shared.global [%0], [%1], 16, %2;" :: "r"(s), "l"(g), "r"(srcsz));
}
#define CP_COMMIT() asm volatile("cp.async.commit_group;" ::: "memory")
#define CP_WAIT(n)  asm volatile("cp.async.wait_group %0;" :: "n"(n) : "memory")

__device__ __forceinline__ void ldsm_x4(uint32_t* r, uint32_t a) {
    asm volatile("ldmatrix.sync.aligned.m8n8.x4.shared.b16 {%0,%1,%2,%3}, [%4];"
        : "=r"(r[0]), "=r"(r[1]), "=r"(r[2]), "=r"(r[3]) : "r"(a));
}
__device__ __forceinline__ void ldsm_x2(uint32_t* r, uint32_t a) {
    asm volatile("ldmatrix.sync.aligned.m8n8.x2.shared.b16 {%0,%1}, [%2];"
        : "=r"(r[0]), "=r"(r[1]) : "r"(a));
}
__device__ __forceinline__ void ldsm_x2t(uint32_t* r, uint32_t a) {
    asm volatile("ldmatrix.sync.aligned.m8n8.x2.trans.shared.b16 {%0,%1}, [%2];"
        : "=r"(r[0]), "=r"(r[1]) : "r"(a));
}
__device__ __forceinline__ void mma_bf16(float* d, const uint32_t* a, const uint32_t* b) {
    asm volatile(
        "mma.sync.aligned.m16n8k16.row.col.f32.bf16.bf16.f32 "
        "{%0,%1,%2,%3}, {%4,%5,%6,%7}, {%8,%9}, {%0,%1,%2,%3};"
        : "+f"(d[0]), "+f"(d[1]), "+f"(d[2]), "+f"(d[3])
        : "r"(a[0]), "r"(a[1]), "r"(a[2]), "r"(a[3]), "r"(b[0]), "r"(b[1]));
}

__device__ __forceinline__ uint32_t pack_bf2(float x, float y) {
    __nv_bfloat162 h;
    h.x = __float2bfloat16(x); h.y = __float2bfloat16(y);
    return *(uint32_t*)&h;
}

// ============================================================
// Conversion kernels
// ============================================================
__global__ __launch_bounds__(256) void convert_x_kernel(const float* __restrict__ x)
{
    size_t off = (size_t)blockIdx.x * DMODEL + threadIdx.x * 4;
    float4 v = *(const float4*)(x + off);
    __nv_bfloat162 h01, h23, l01, l23;
    h01.x = __float2bfloat16(v.x); l01.x = __float2bfloat16(v.x - __bfloat162float(h01.x));
    h01.y = __float2bfloat16(v.y); l01.y = __float2bfloat16(v.y - __bfloat162float(h01.y));
    h23.x = __float2bfloat16(v.z); l23.x = __float2bfloat16(v.z - __bfloat162float(h23.x));
    h23.y = __float2bfloat16(v.w); l23.y = __float2bfloat16(v.w - __bfloat162float(h23.y));
    *(__nv_bfloat162*)(g_xh + off) = h01; *(__nv_bfloat162*)(g_xh + off + 2) = h23;
    *(__nv_bfloat162*)(g_xl + off) = l01; *(__nv_bfloat162*)(g_xl + off + 2) = l23;
}

// transpose W[k][n] -> Wt[n][k], split hi/lo. block (32,8), tile 32x32
__global__ __launch_bounds__(256) void transpose_w_kernel(
    const float* __restrict__ Wq, const float* __restrict__ Wk,
    const float* __restrict__ Wv, const float* __restrict__ Wo)
{
    __shared__ float tile[32][33];
    int z = blockIdx.z;
    const float* W = (z == 0) ? Wq : (z == 1) ? Wk : (z == 2) ? Wv : Wo;
    __nv_bfloat16* Th = g_wh + (size_t)z * WSZ;
    __nv_bfloat16* Tl = g_wl + (size_t)z * WSZ;
    int kb = blockIdx.y * 32, nb = blockIdx.x * 32;
    int tx = threadIdx.x, ty = threadIdx.y;
#pragma unroll
    for (int i = 0; i < 4; i++)
        tile[ty + 8 * i][tx] = W[(size_t)(kb + ty + 8 * i) * DMODEL + nb + tx];
    __syncthreads();
#pragma unroll
    for (int i = 0; i < 4; i++) {
        float v = tile[tx][ty + 8 * i];
        __nv_bfloat16 h = __float2bfloat16(v);
        __nv_bfloat16 l = __float2bfloat16(v - __bfloat162float(h));
        size_t o = (size_t)(nb + ty + 8 * i) * DMODEL + kb + tx;
        Th[o] = h; Tl[o] = l;
    }
}

// ============================================================
// Split-bf16 HMMA GEMM (R4-proven: 2-stage, 80KB smem, x2 B-frags)
// CTA tile 128x128, BK=32, 8 warps (2x4), warp tile 64x32.
// ============================================================
#define BK       32
#define PITCHE   40
#define PITCHB   (PITCHE*2)            // 80 bytes
#define MAT_B    (128*PITCHB)          // 10240 B
#define STAGE_B2 (4*MAT_B)             // 40960 B per stage
#define GEMM_SMEM (2*STAGE_B2)         // 81920 B
#define ROW64B   (64*PITCHB)

__global__ __launch_bounds__(256) void hmma_gemm_kernel(
    int mode, const float* __restrict__ b0, const float* __restrict__ b1,
    const float* __restrict__ b2, float* __restrict__ outp)
{
    extern __shared__ char sm[];
    const uint32_t sbase = smem_u32(sm);

    const int tid  = threadIdx.x;
    const int lane = tid & 31;
    const int wid  = tid >> 5;
    const int wm   = wid >> 2;
    const int wn   = wid & 3;
    const int m0   = blockIdx.y * 128;
    const int n0   = blockIdx.x * 128;
    const int z    = blockIdx.z;

    const __nv_bfloat16 *Ah, *Al, *Bh, *Bl;
    const float* bias;
    if (mode == 0) {
        Ah = g_xh; Al = g_xl;
        Bh = g_wh + (size_t)z * WSZ; Bl = g_wl + (size_t)z * WSZ;
        bias = (z == 0) ? b0 : (z == 1) ? b1 : b2;
    } else {
        Ah = g_ah; Al = g_al;
        Bh = g_wh + 3ull * WSZ; Bl = g_wl + 3ull * WSZ;
        bias = b0;
    }

    const int rowA = tid >> 2;
    const int seg  = tid & 3;
    const uint32_t s0 = (uint32_t)rowA * PITCHB + (uint32_t)seg * 16;
    const __nv_bfloat16* pAh = Ah + (size_t)(m0 + rowA) * DMODEL + seg * 8;
    const __nv_bfloat16* pAl = Al + (size_t)(m0 + rowA) * DMODEL + seg * 8;
    const __nv_bfloat16* pBh = Bh + (size_t)(n0 + rowA) * DMODEL + seg * 8;
    const __nv_bfloat16* pBl = Bl + (size_t)(n0 + rowA) * DMODEL + seg * 8;

#define PREFETCH(stage, cc) do {                                             \
    const int _k0 = (cc) * BK;                                               \
    const uint32_t _sb = sbase + (uint32_t)(stage) * STAGE_B2 + s0;          \
    cp_async16(_sb,                      pAh + _k0);                         \
    cp_async16(_sb + ROW64B,             pAh + 64 * DMODEL + _k0);           \
    cp_async16(_sb + MAT_B,              pAl + _k0);                         \
    cp_async16(_sb + MAT_B + ROW64B,     pAl + 64 * DMODEL + _k0);           \
    cp_async16(_sb + 2 * MAT_B,          pBh + _k0);                         \
    cp_async16(_sb + 2 * MAT_B + ROW64B, pBh + 64 * DMODEL + _k0);           \
    cp_async16(_sb + 3 * MAT_B,          pBl + _k0);                         \
    cp_async16(_sb + 3 * MAT_B + ROW64B, pBl + 64 * DMODEL + _k0);           \
} while (0)

    float acc[4][4][4];
#pragma unroll
    for (int i = 0; i < 4; i++)
#pragma unroll
        for (int j = 0; j < 4; j++)
#pragma unroll
            for (int e = 0; e < 4; e++) acc[i][j][e] = 0.f;

    const int arow_l = ((lane >> 3) & 1) * 8 + (lane & 7);
    const int akoff  = (lane >> 4) * 8;
    const int brow_l = lane & 7;
    const int bkoff  = ((lane >> 3) & 1) * 8;

    PREFETCH(0, 0);
    CP_COMMIT();

    const int NCHUNK = DMODEL / BK;   // 32
    for (int c = 0; c < NCHUNK; c++) {
        const int s = c & 1;
        if (c < NCHUNK - 1) { PREFETCH(s ^ 1, c + 1); CP_COMMIT(); CP_WAIT(1); }
        else                { CP_WAIT(0); }
        __syncthreads();

        const uint32_t stb = sbase + (uint32_t)s * STAGE_B2;
#pragma unroll
        for (int ks = 0; ks < 2; ks++) {
            uint32_t ah[4][4], al[4][4], bh[4][2], bl[4][2];
#pragma unroll
            for (int mt = 0; mt < 4; mt++) {
                uint32_t ad = stb + (uint32_t)(wm * 64 + mt * 16 + arow_l) * PITCHB
                                  + (uint32_t)(ks * 16 + akoff) * 2;
                ldsm_x4(ah[mt], ad);
                ldsm_x4(al[mt], ad + MAT_B);
            }
#pragma unroll
            for (int nt = 0; nt < 4; nt++) {
                uint32_t bd = stb + 2 * MAT_B
                                  + (uint32_t)(wn * 32 + nt * 8 + brow_l) * PITCHB
                                  + (uint32_t)(ks * 16 + bkoff) * 2;
                ldsm_x2(bh[nt], bd);
                ldsm_x2(bl[nt], bd + MAT_B);
            }
#pragma unroll
            for (int mt = 0; mt < 4; mt++)
#pragma unroll
                for (int nt = 0; nt < 4; nt++) {
                    mma_bf16(acc[mt][nt], ah[mt], bh[nt]);
                    mma_bf16(acc[mt][nt], ah[mt], bl[nt]);
                    mma_bf16(acc[mt][nt], al[mt], bh[nt]);
                }
        }
        __syncthreads();
    }

    const int g     = lane >> 2;
    const int cpair = (lane & 3) * 2;
    if (mode == 0) {
        __nv_bfloat16* Ch = (z == 0) ? g_qh : (z == 1) ? g_kh : g_vh;
        __nv_bfloat16* Cl = (z == 0) ? g_ql : (z == 1) ? g_kl : g_vl;
#pragma unroll
        for (int mt = 0; mt < 4; mt++) {
            int row0 = m0 + wm * 64 + mt * 16 + g;
#pragma unroll
            for (int nt = 0; nt < 4; nt++) {
                int col = n0 + wn * 32 + nt * 8 + cpair;
                float bx = bias[col], by = bias[col + 1];
#pragma unroll
                for (int rr = 0; rr < 2; rr++) {
                    float o0 = acc[mt][nt][rr * 2 + 0] + bx;
                    float o1 = acc[mt][nt][rr * 2 + 1] + by;
                    __nv_bfloat162 h2, l2;
                    h2.x = __float2bfloat16(o0); l2.x = __float2bfloat16(o0 - __bfloat162float(h2.x));
                    h2.y = __float2bfloat16(o1); l2.y = __float2bfloat16(o1 - __bfloat162float(h2.y));
                    size_t off = (size_t)(row0 + rr * 8) * DMODEL + col;
                    *(__nv_bfloat162*)(Ch + off) = h2;
                    *(__nv_bfloat162*)(Cl + off) = l2;
                }
            }
        }
    } else {
        float* C = outp;
#pragma unroll
        for (int mt = 0; mt < 4; mt++) {
            int row0 = m0 + wm * 64 + mt * 16 + g;
#pragma unroll
            for (int nt = 0; nt < 4; nt++) {
                int col = n0 + wn * 32 + nt * 8 + cpair;
                float bx = bias[col], by = bias[col + 1];
                *(float2*)(C + (size_t)row0 * DMODEL + col) =
                    make_float2(acc[mt][nt][0] + bx, acc[mt][nt][1] + by);
                *(float2*)(C + (size_t)(row0 + 8) * DMODEL + col) =
                    make_float2(acc[mt][nt][2] + bx, acc[mt][nt][3] + by);
            }
        }
    }
#undef PREFETCH
}

// ============================================================
// Banded flash-attention with mma.sync (split bf16 hi/lo)
// CTA = (128 queries, head, batch); 8 warps; warp = 16 query rows.
// K/V band = 256 rows; per-warp valid band = 144 keys = 18 n-tiles.
// ============================================================
#define APITCHB  144
#define A_QH     0
#define A_QL     18432              // 128*144
#define A_KH     36864
#define A_KL     73728              // +256*144
#define A_VH     110592
#define A_VL     147456
#define ATTN_SMEM 184320

__global__ __launch_bounds__(256) void attn_mma_kernel()
{
    extern __shared__ char sm[];
    const uint32_t sb = smem_u32(sm);

    const int tid  = threadIdx.x;
    const int lane = tid & 31;
    const int w    = tid >> 5;          // 0..7
    const int b    = blockIdx.z;
    const int h    = blockIdx.y;
    const int q0   = blockIdx.x * 128;
    const int kbase = q0 - WIN;
    const size_t tok0 = (size_t)b * SEQ;
    const int coff = h * HDIM;

    // ---- group 0: Q (128 rows) + K (256 rows); group 1: V (256 rows) ----
#pragma unroll
    for (int i = 0; i < 4; i++) {
        int task = tid + i * 256;          // 1024 tasks
        int row = task >> 3, seg = task & 7;
        uint32_t d = sb + A_QH + (uint32_t)row * APITCHB + (uint32_t)seg * 16;
        size_t goff = (tok0 + q0 + row) * DMODEL + coff + seg * 8;
        cp_async16(d,                 g_qh + goff);
        cp_async16(d + (A_QL - A_QH), g_ql + goff);
    }
#pragma unroll
    for (int i = 0; i < 8; i++) {
        int task = tid + i * 256;          // 2048 tasks
        int row = task >> 3, seg = task & 7;
        int kg = kbase + row;
        int kgc = min(max(kg, 0), SEQ - 1);
        uint32_t sz = (kg >= 0 && kg < SEQ) ? 16u : 0u;
        uint32_t d = sb + A_KH + (uint32_t)row * APITCHB + (uint32_t)seg * 16;
        size_t goff = (tok0 + kgc) * DMODEL + coff + seg * 8;
        cp_async16z(d,                 g_kh + goff, sz);
        cp_async16z(d + (A_KL - A_KH), g_kl + goff, sz);
    }
    CP_COMMIT();
#pragma unroll
    for (int i = 0; i < 8; i++) {
        int task = tid + i * 256;
        int row = task >> 3, seg = task & 7;
        int kg = kbase + row;
        int kgc = min(max(kg, 0), SEQ - 1);
        uint32_t sz = (kg >= 0 && kg < SEQ) ? 16u : 0u;
        uint32_t d = sb + A_VH + (uint32_t)row * APITCHB + (uint32_t)seg * 16;
        size_t goff = (tok0 + kgc) * DMODEL + coff + seg * 8;
        cp_async16z(d,                 g_vh + goff, sz);
        cp_async16z(d + (A_VL - A_VH), g_vl + goff, sz);
    }
    CP_COMMIT();

    CP_WAIT(1);
    __syncthreads();

    // ---- Q fragments ----
    const int arow = w * 16 + ((lane >> 3) & 1) * 8 + (lane & 7);
    const int akoff = (lane >> 4) * 8;
    uint32_t qfh[4][4], qfl[4][4];
#pragma unroll
    for (int kc = 0; kc < 4; kc++) {
        uint32_t ad = sb + A_QH + (uint32_t)arow * APITCHB + (uint32_t)(kc * 16 + akoff) * 2;
        ldsm_x4(qfh[kc], ad);
        ldsm_x4(qfl[kc], ad + (A_QL - A_QH));
    }

    // ---- QK: S[16][144], 18 n-tiles processed as 9 pairs via ldsm_x4 ----
    float s[18][4];
#pragma unroll
    for (int t = 0; t < 18; t++)
#pragma unroll
        for (int e = 0; e < 4; e++) s[t][e] = 0.f;

    const int krow4 = (lane & 7) + ((lane >> 4) << 3);
    const int kko4  = ((lane >> 3) & 1) * 16;       // bytes
#pragma unroll
    for (int u = 0; u < 9; u++) {
        int ntb = 2 * w + 2 * u;
        uint32_t kb_addr = sb + A_KH + (uint32_t)(ntb * 8 + krow4) * APITCHB + (uint32_t)kko4;
#pragma unroll
        for (int kc = 0; kc < 4; kc++) {
            uint32_t kh4[4], kl4[4];
            uint32_t ka = kb_addr + (uint32_t)kc * 32;
            ldsm_x4(kh4, ka);
            ldsm_x4(kl4, ka + (A_KL - A_KH));
            uint32_t bh0[2] = { kh4[0], kh4[1] }, bh1[2] = { kh4[2], kh4[3] };
            uint32_t bl0[2] = { kl4[0], kl4[1] }, bl1[2] = { kl4[2], kl4[3] };
            mma_bf16(s[2 * u],     qfh[kc], bh0);
            mma_bf16(s[2 * u],     qfh[kc], bl0);
            mma_bf16(s[2 * u],     qfl[kc], bh0);
            mma_bf16(s[2 * u + 1], qfh[kc], bh1);
            mma_bf16(s[2 * u + 1], qfh[kc], bl1);
            mma_bf16(s[2 * u + 1], qfl[kc], bh1);
        }
    }

    // ---- mask + softmax ----
    const int g  = lane >> 2;
    const int c2 = (lane & 3) * 2;
    const int qg0 = q0 + w * 16 + g;
    const int qg1 = qg0 + 8;
    const float scale = 0.125f;

    float m0 = -1e30f, m1 = -1e30f;
#pragma unroll
    for (int t = 0; t < 18; t++) {
        int j0 = (2 * w + t) * 8 + c2;
        int kg0 = kbase + j0, kg1 = kg0 + 1;
        bool in0 = (kg0 >= 0) && (kg0 < SEQ);
        bool in1 = (kg1 >= 0) && (kg1 < SEQ);
        int d00 = kg0 - qg0, d10 = kg1 - qg0, d01 = kg0 - qg1, d11 = kg1 - qg1;
        s[t][0] = (in0 && d00 <= WIN && d00 >= -WIN) ? s[t][0] * scale : -1e30f;
        s[t][1] = (in1 && d10 <= WIN && d10 >= -WIN) ? s[t][1] * scale : -1e30f;
        s[t][2] = (in0 && d01 <= WIN && d01 >= -WIN) ? s[t][2] * scale : -1e30f;
        s[t][3] = (in1 && d11 <= WIN && d11 >= -WIN) ? s[t][3] * scale : -1e30f;
        m0 = fmaxf(m0, fmaxf(s[t][0], s[t][1]));
        m1 = fmaxf(m1, fmaxf(s[t][2], s[t][3]));
    }
    m0 = fmaxf(m0, __shfl_xor_sync(0xffffffffu, m0, 1));
    m0 = fmaxf(m0, __shfl_xor_sync(0xffffffffu, m0, 2));
    m1 = fmaxf(m1, __shfl_xor_sync(0xffffffffu, m1, 1));
    m1 = fmaxf(m1, __shfl_xor_sync(0xffffffffu, m1, 2));

    float r0 = 0.f, r1 = 0.f;
#pragma unroll
    for (int t = 0; t < 18; t++) {
        s[t][0] = __expf(s[t][0] - m0);
        s[t][1] = __expf(s[t][1] - m0);
        s[t][2] = __expf(s[t][2] - m1);
        s[t][3] = __expf(s[t][3] - m1);
        r0 += s[t][0] + s[t][1];
        r1 += s[t][2] + s[t][3];
    }
    r0 += __shfl_xor_sync(0xffffffffu, r0, 1);
    r0 += __shfl_xor_sync(0xffffffffu, r0, 2);
    r1 += __shfl_xor_sync(0xffffffffu, r1, 1);
    r1 += __shfl_xor_sync(0xffffffffu, r1, 2);
    float inv0 = 1.f / r0, inv1 = 1.f / r1;

    uint32_t ph01[18], ph23[18], pl01[18], pl23[18];
#pragma unroll
    for (int t = 0; t < 18; t++) {
        float p0 = s[t][0] * inv0, p1 = s[t][1] * inv0;
        float p2 = s[t][2] * inv1, p3 = s[t][3] * inv1;
        __nv_bfloat162 h2;
        h2.x = __float2bfloat16(p0); h2.y = __float2bfloat16(p1);
        ph01[t] = *(uint32_t*)&h2;
        pl01[t] = pack_bf2(p0 - __bfloat162float(h2.x), p1 - __bfloat162float(h2.y));
        h2.x = __float2bfloat16(p2); h2.y = __float2bfloat16(p3);
        ph23[t] = *(uint32_t*)&h2;
        pl23[t] = pack_bf2(p2 - __bfloat162float(h2.x), p3 - __bfloat162float(h2.y));
    }

    CP_WAIT(0);
    __syncthreads();

    // ---- PV: out[16][64] ----
    float o[8][4];
#pragma unroll
    for (int nt = 0; nt < 8; nt++)
#pragma unroll
        for (int e = 0; e < 4; e++) o[nt][e] = 0.f;

    const int vrow_l = ((lane >> 3) & 1) * 8 + (lane & 7);
#pragma unroll
    for (int jl = 0; jl < 9; jl++) {
        uint32_t ah[4] = { ph01[2 * jl], ph23[2 * jl], ph01[2 * jl + 1], ph23[2 * jl + 1] };
        uint32_t al[4] = { pl01[2 * jl], pl23[2 * jl], pl01[2 * jl + 1], pl23[2 * jl + 1] };
        int keyb = (w + jl) * 16;
        uint32_t va_base = sb + A_VH + (uint32_t)(keyb + vrow_l) * APITCHB;
#pragma unroll
        for (int nt = 0; nt < 8; nt++) {
            uint32_t vfh[2], vfl[2];
            uint32_t va = va_base + (uint32_t)nt * 16;
            ldsm_x2t(vfh, va);
            ldsm_x2t(vfl, va + (A_VL - A_VH));
            mma_bf16(o[nt], ah, vfh);
            mma_bf16(o[nt], ah, vfl);
            mma_bf16(o[nt], al, vfh);
        }
    }

    size_t row0 = tok0 + qg0;
    size_t row1 = tok0 + qg1;
#pragma unroll
    for (int nt = 0; nt < 8; nt++) {
        int col = coff + nt * 8 + c2;
        __nv_bfloat162 h2, l2;
        h2.x = __float2bfloat16(o[nt][0]); l2.x = __float2bfloat16(o[nt][0] - __bfloat162float(h2.x));
        h2.y = __float2bfloat16(o[nt][1]); l2.y = __float2bfloat16(o[nt][1] - __bfloat162float(h2.y));
        *(__nv_bfloat162*)(g_ah + row0 * DMODEL + col) = h2;
        *(__nv_bfloat162*)(g_al + row0 * DMODEL + col) = l2;
        h2.x = __float2bfloat16(o[nt][2]); l2.x = __float2bfloat16(o[nt][2] - __bfloat162float(h2.x));
        h2.y = __float2bfloat16(o[nt][3]); l2.y = __float2bfloat16(o[nt][3] - __bfloat162float(h2.y));
        *(__nv_bfloat162*)(g_ah + row1 * DMODEL + col) = h2;
        *(__nv_bfloat162*)(g_al + row1 * DMODEL + col) = l2;
    }
}

// ============================================================
extern "C" void kernel_launch(void* const* d_in, const int* in_sizes, int n_in,
                              void* d_out, int out_size)
{
    const float* x  = (const float*)d_in[0];
    const float* Wq = (const float*)d_in[1];
    const float* bq = (const float*)d_in[2];
    const float* Wk = (const float*)d_in[3];
    const float* bk = (const float*)d_in[4];
    const float* Wv = (const float*)d_in[5];
    const float* bv = (const float*)d_in[6];
    const float* Wo = (const float*)d_in[7];
    const float* bo = (const float*)d_in[8];
    float* out = (float*)d_out;

    cudaFuncSetAttribute(hmma_gemm_kernel, cudaFuncAttributeMaxDynamicSharedMemorySize, GEMM_SMEM);
    cudaFuncSetAttribute(attn_mma_kernel, cudaFuncAttributeMaxDynamicSharedMemorySize, ATTN_SMEM);

    convert_x_kernel<<<MTOT, 256>>>(x);
    transpose_w_kernel<<<dim3(32, 32, 4), dim3(32, 8)>>>(Wq, Wk, Wv, Wo);

    dim3 gq(DMODEL / 128, MTOT / 128, 3);
    hmma_gemm_kernel<<<gq, 256, GEMM_SMEM>>>(0, bq, bk, bv, nullptr);

    dim3 ga(SEQ / 128, NHEADS, BATCH);
    attn_mma_kernel<<<ga, 256, ATTN_SMEM>>>();

    dim3 go(DMODEL / 128, MTOT / 128, 1);
    hmma_gemm_kernel<<<go, 256, GEMM_SMEM>>>(1, bo, nullptr, nullptr, out);
}

// round 8
// speedup vs baseline: 1.4951x; 1.3421x over previous
#include <cuda_runtime.h>
#include <cuda_bf16.h>
#include <cuda_fp16.h>
#include <math.h>
#include <stdint.h>

#define BATCH   2
#define SEQ     2048
#define DMODEL  1024
#define NHEADS  16
#define HDIM    64
#define WIN     64
#define MTOT    (BATCH*SEQ)   // 4096
#define WSZ     (DMODEL*DMODEL)

// ---------------- scratch (static device globals) ----------------
__device__ __half g_x16[MTOT*DMODEL];          // x rounded to fp16
__device__ __half g_wh[4*WSZ];                 // transposed [n][k], fp16 hi
__device__ __half g_wl[4*WSZ];                 // transposed [n][k], fp16 lo
__device__ __nv_bfloat16 g_qh[MTOT*DMODEL];
__device__ __nv_bfloat16 g_ql[MTOT*DMODEL];
__device__ __nv_bfloat16 g_kh[MTOT*DMODEL];
__device__ __nv_bfloat16 g_kl[MTOT*DMODEL];
__device__ __nv_bfloat16 g_vh[MTOT*DMODEL];
__device__ __nv_bfloat16 g_vl[MTOT*DMODEL];
__device__ __half g_a16[MTOT*DMODEL];          // attention out, fp16

// ---------------- PTX helpers (non-'a' features only) ----------------
__device__ __forceinline__ uint32_t smem_u32(const void* p) {
    uint32_t a;
    asm("{ .reg .u64 t; cvta.to.shared.u64 t, %1; cvt.u32.u64 %0, t; }" : "=r"(a) : "l"(p));
    return a;
}
__device__ __forceinline__ void cp_async16(uint32_t s, const void* g) {
    asm volatile("cp.async.cg.shared.global [%0], [%1], 16;" :: "r"(s), "l"(g));
}
__device__ __forceinline__ void cp_async16z(uint32_t s, const void* g, uint32_t srcsz) {
    asm volatile("cp.async.cg.shared.global [%0], [%1], 16, %2;" :: "r"(s), "l"(g), "r"(srcsz));
}
#define CP_COMMIT() asm volatile("cp.async.commit_group;" ::: "memory")
#define CP_WAIT(n)  asm volatile("cp.async.wait_group %0;" :: "n"(n) : "memory")

__device__ __forceinline__ void ldsm_x4(uint32_t* r, uint32_t a) {
    asm volatile("ldmatrix.sync.aligned.m8n8.x4.shared.b16 {%0,%1,%2,%3}, [%4];"
        : "=r"(r[0]), "=r"(r[1]), "=r"(r[2]), "=r"(r[3]) : "r"(a));
}
__device__ __forceinline__ void ldsm_x2(uint32_t* r, uint32_t a) {
    asm volatile("ldmatrix.sync.aligned.m8n8.x2.shared.b16 {%0,%1}, [%2];"
        : "=r"(r[0]), "=r"(r[1]) : "r"(a));
}
__device__ __forceinline__ void ldsm_x2t(uint32_t* r, uint32_t a) {
    asm volatile("ldmatrix.sync.aligned.m8n8.x2.trans.shared.b16 {%0,%1}, [%2];"
        : "=r"(r[0]), "=r"(r[1]) : "r"(a));
}
__device__ __forceinline__ void mma_bf16(float* d, const uint32_t* a, const uint32_t* b) {
    asm volatile(
        "mma.sync.aligned.m16n8k16.row.col.f32.bf16.bf16.f32 "
        "{%0,%1,%2,%3}, {%4,%5,%6,%7}, {%8,%9}, {%0,%1,%2,%3};"
        : "+f"(d[0]), "+f"(d[1]), "+f"(d[2]), "+f"(d[3])
        : "r"(a[0]), "r"(a[1]), "r"(a[2]), "r"(a[3]), "r"(b[0]), "r"(b[1]));
}
__device__ __forceinline__ void mma_f16(float* d, const uint32_t* a, const uint32_t* b) {
    asm volatile(
        "mma.sync.aligned.m16n8k16.row.col.f32.f16.f16.f32 "
        "{%0,%1,%2,%3}, {%4,%5,%6,%7}, {%8,%9}, {%0,%1,%2,%3};"
        : "+f"(d[0]), "+f"(d[1]), "+f"(d[2]), "+f"(d[3])
        : "r"(a[0]), "r"(a[1]), "r"(a[2]), "r"(a[3]), "r"(b[0]), "r"(b[1]));
}

__device__ __forceinline__ uint32_t pack_bf2(float x, float y) {
    __nv_bfloat162 h;
    h.x = __float2bfloat16(x); h.y = __float2bfloat16(y);
    return *(uint32_t*)&h;
}

// ============================================================
// Conversion kernels
// ============================================================
__global__ __launch_bounds__(256) void convert_x_kernel(const float* __restrict__ x)
{
    size_t off = (size_t)blockIdx.x * DMODEL + threadIdx.x * 4;
    float4 v = *(const float4*)(x + off);
    __half2 a = __floats2half2_rn(v.x, v.y);
    __half2 b = __floats2half2_rn(v.z, v.w);
    *(__half2*)(g_x16 + off)     = a;
    *(__half2*)(g_x16 + off + 2) = b;
}

// transpose W[k][n] -> Wt[n][k], split fp16 hi/lo. block (32,8), tile 32x32
__global__ __launch_bounds__(256) void transpose_w_kernel(
    const float* __restrict__ Wq, const float* __restrict__ Wk,
    const float* __restrict__ Wv, const float* __restrict__ Wo)
{
    __shared__ float tile[32][33];
    int z = blockIdx.z;
    const float* W = (z == 0) ? Wq : (z == 1) ? Wk : (z == 2) ? Wv : Wo;
    __half* Th = g_wh + (size_t)z * WSZ;
    __half* Tl = g_wl + (size_t)z * WSZ;
    int kb = blockIdx.y * 32, nb = blockIdx.x * 32;
    int tx = threadIdx.x, ty = threadIdx.y;
#pragma unroll
    for (int i = 0; i < 4; i++)
        tile[ty + 8 * i][tx] = W[(size_t)(kb + ty + 8 * i) * DMODEL + nb + tx];
    __syncthreads();
#pragma unroll
    for (int i = 0; i < 4; i++) {
        float v = tile[tx][ty + 8 * i];
        __half h = __float2half_rn(v);
        __half l = __float2half_rn(v - __half2float(h));
        size_t o = (size_t)(nb + ty + 8 * i) * DMODEL + kb + tx;
        Th[o] = h; Tl[o] = l;
    }
}

// ============================================================
// 2-pass split-fp16 HMMA GEMM: C = A16 @ (Wh+Wl)^T + bias
// CTA tile 128x128, BK=32, 8 warps (2x4), warp tile 64x32.
// 2-stage cp.async, stage = A(10240) + Bh(10240) + Bl(10240) = 30720 B.
// ============================================================
#define BK       32
#define PITCHB   80                    // bytes per SMEM row (40 fp16)
#define MAT_B    (128*PITCHB)          // 10240 B per matrix tile
#define STAGE_B2 (3*MAT_B)             // 30720 B per stage
#define GEMM_SMEM (2*STAGE_B2)         // 61440 B
#define ROW64B   (64*PITCHB)

__global__ __launch_bounds__(256) void hmma_gemm_kernel(
    int mode, const float* __restrict__ b0, const float* __restrict__ b1,
    const float* __restrict__ b2, float* __restrict__ outp)
{
    extern __shared__ char sm[];
    const uint32_t sbase = smem_u32(sm);

    const int tid  = threadIdx.x;
    const int lane = tid & 31;
    const int wid  = tid >> 5;
    const int wm   = wid >> 2;
    const int wn   = wid & 3;
    const int m0   = blockIdx.y * 128;
    const int n0   = blockIdx.x * 128;
    const int z    = blockIdx.z;

    const __half *A, *Bh, *Bl;
    const float* bias;
    if (mode == 0) {
        A = g_x16;
        Bh = g_wh + (size_t)z * WSZ; Bl = g_wl + (size_t)z * WSZ;
        bias = (z == 0) ? b0 : (z == 1) ? b1 : b2;
    } else {
        A = g_a16;
        Bh = g_wh + 3ull * WSZ; Bl = g_wl + 3ull * WSZ;
        bias = b0;
    }

    const int rowA = tid >> 2;
    const int seg  = tid & 3;
    const uint32_t s0 = (uint32_t)rowA * PITCHB + (uint32_t)seg * 16;
    const __half* pA  = A  + (size_t)(m0 + rowA) * DMODEL + seg * 8;
    const __half* pBh = Bh + (size_t)(n0 + rowA) * DMODEL + seg * 8;
    const __half* pBl = Bl + (size_t)(n0 + rowA) * DMODEL + seg * 8;

#define PREFETCH(stage, cc) do {                                             \
    const int _k0 = (cc) * BK;                                               \
    const uint32_t _sb = sbase + (uint32_t)(stage) * STAGE_B2 + s0;          \
    cp_async16(_sb,                      pA  + _k0);                         \
    cp_async16(_sb + ROW64B,             pA  + 64 * DMODEL + _k0);           \
    cp_async16(_sb + MAT_B,              pBh + _k0);                         \
    cp_async16(_sb + MAT_B + ROW64B,     pBh + 64 * DMODEL + _k0);           \
    cp_async16(_sb + 2 * MAT_B,          pBl + _k0);                         \
    cp_async16(_sb + 2 * MAT_B + ROW64B, pBl + 64 * DMODEL + _k0);           \
} while (0)

    float acc[4][4][4];
#pragma unroll
    for (int i = 0; i < 4; i++)
#pragma unroll
        for (int j = 0; j < 4; j++)
#pragma unroll
            for (int e = 0; e < 4; e++) acc[i][j][e] = 0.f;

    const int arow_l = ((lane >> 3) & 1) * 8 + (lane & 7);
    const int akoff  = (lane >> 4) * 8;
    const int brow_l = lane & 7;
    const int bkoff  = ((lane >> 3) & 1) * 8;

    PREFETCH(0, 0);
    CP_COMMIT();

    const int NCHUNK = DMODEL / BK;   // 32
    for (int c = 0; c < NCHUNK; c++) {
        const int s = c & 1;
        if (c < NCHUNK - 1) { PREFETCH(s ^ 1, c + 1); CP_COMMIT(); CP_WAIT(1); }
        else                { CP_WAIT(0); }
        __syncthreads();

        const uint32_t stb = sbase + (uint32_t)s * STAGE_B2;
#pragma unroll
        for (int ks = 0; ks < 2; ks++) {
            uint32_t a[4][4], bh[4][2], bl[4][2];
#pragma unroll
            for (int mt = 0; mt < 4; mt++) {
                uint32_t ad = stb + (uint32_t)(wm * 64 + mt * 16 + arow_l) * PITCHB
                                  + (uint32_t)(ks * 16 + akoff) * 2;
                ldsm_x4(a[mt], ad);
            }
#pragma unroll
            for (int nt = 0; nt < 4; nt++) {
                uint32_t bd = stb + MAT_B
                                  + (uint32_t)(wn * 32 + nt * 8 + brow_l) * PITCHB
                                  + (uint32_t)(ks * 16 + bkoff) * 2;
                ldsm_x2(bh[nt], bd);
                ldsm_x2(bl[nt], bd + MAT_B);
            }
#pragma unroll
            for (int mt = 0; mt < 4; mt++)
#pragma unroll
                for (int nt = 0; nt < 4; nt++) {
                    mma_f16(acc[mt][nt], a[mt], bh[nt]);
                    mma_f16(acc[mt][nt], a[mt], bl[nt]);
                }
        }
        __syncthreads();
    }

    const int g     = lane >> 2;
    const int cpair = (lane & 3) * 2;
    if (mode == 0) {
        __nv_bfloat16* Ch = (z == 0) ? g_qh : (z == 1) ? g_kh : g_vh;
        __nv_bfloat16* Cl = (z == 0) ? g_ql : (z == 1) ? g_kl : g_vl;
#pragma unroll
        for (int mt = 0; mt < 4; mt++) {
            int row0 = m0 + wm * 64 + mt * 16 + g;
#pragma unroll
            for (int nt = 0; nt < 4; nt++) {
                int col = n0 + wn * 32 + nt * 8 + cpair;
                float bx = bias[col], by = bias[col + 1];
#pragma unroll
                for (int rr = 0; rr < 2; rr++) {
                    float o0 = acc[mt][nt][rr * 2 + 0] + bx;
                    float o1 = acc[mt][nt][rr * 2 + 1] + by;
                    __nv_bfloat162 h2, l2;
                    h2.x = __float2bfloat16(o0); l2.x = __float2bfloat16(o0 - __bfloat162float(h2.x));
                    h2.y = __float2bfloat16(o1); l2.y = __float2bfloat16(o1 - __bfloat162float(h2.y));
                    size_t off = (size_t)(row0 + rr * 8) * DMODEL + col;
                    *(__nv_bfloat162*)(Ch + off) = h2;
                    *(__nv_bfloat162*)(Cl + off) = l2;
                }
            }
        }
    } else {
        float* C = outp;
#pragma unroll
        for (int mt = 0; mt < 4; mt++) {
            int row0 = m0 + wm * 64 + mt * 16 + g;
#pragma unroll
            for (int nt = 0; nt < 4; nt++) {
                int col = n0 + wn * 32 + nt * 8 + cpair;
                float bx = bias[col], by = bias[col + 1];
                *(float2*)(C + (size_t)row0 * DMODEL + col) =
                    make_float2(acc[mt][nt][0] + bx, acc[mt][nt][1] + by);
                *(float2*)(C + (size_t)(row0 + 8) * DMODEL + col) =
                    make_float2(acc[mt][nt][2] + bx, acc[mt][nt][3] + by);
            }
        }
    }
#undef PREFETCH
}

// ============================================================
// Banded flash-attention with mma.sync (split bf16 hi/lo)
// CTA = (128 queries, head, batch); 8 warps; warp = 16 query rows.
// ============================================================
#define APITCHB  144
#define A_QH     0
#define A_QL     18432              // 128*144
#define A_KH     36864
#define A_KL     73728              // +256*144
#define A_VH     110592
#define A_VL     147456
#define ATTN_SMEM 184320

__global__ __launch_bounds__(256) void attn_mma_kernel()
{
    extern __shared__ char sm[];
    const uint32_t sb = smem_u32(sm);

    const int tid  = threadIdx.x;
    const int lane = tid & 31;
    const int w    = tid >> 5;          // 0..7
    const int b    = blockIdx.z;
    const int h    = blockIdx.y;
    const int q0   = blockIdx.x * 128;
    const int kbase = q0 - WIN;
    const size_t tok0 = (size_t)b * SEQ;
    const int coff = h * HDIM;

#pragma unroll
    for (int i = 0; i < 4; i++) {
        int task = tid + i * 256;
        int row = task >> 3, seg = task & 7;
        uint32_t d = sb + A_QH + (uint32_t)row * APITCHB + (uint32_t)seg * 16;
        size_t goff = (tok0 + q0 + row) * DMODEL + coff + seg * 8;
        cp_async16(d,                 g_qh + goff);
        cp_async16(d + (A_QL - A_QH), g_ql + goff);
    }
#pragma unroll
    for (int i = 0; i < 8; i++) {
        int task = tid + i * 256;
        int row = task >> 3, seg = task & 7;
        int kg = kbase + row;
        int kgc = min(max(kg, 0), SEQ - 1);
        uint32_t sz = (kg >= 0 && kg < SEQ) ? 16u : 0u;
        uint32_t d = sb + A_KH + (uint32_t)row * APITCHB + (uint32_t)seg * 16;
        size_t goff = (tok0 + kgc) * DMODEL + coff + seg * 8;
        cp_async16z(d,                 g_kh + goff, sz);
        cp_async16z(d + (A_KL - A_KH), g_kl + goff, sz);
    }
    CP_COMMIT();
#pragma unroll
    for (int i = 0; i < 8; i++) {
        int task = tid + i * 256;
        int row = task >> 3, seg = task & 7;
        int kg = kbase + row;
        int kgc = min(max(kg, 0), SEQ - 1);
        uint32_t sz = (kg >= 0 && kg < SEQ) ? 16u : 0u;
        uint32_t d = sb + A_VH + (uint32_t)row * APITCHB + (uint32_t)seg * 16;
        size_t goff = (tok0 + kgc) * DMODEL + coff + seg * 8;
        cp_async16z(d,                 g_vh + goff, sz);
        cp_async16z(d + (A_VL - A_VH), g_vl + goff, sz);
    }
    CP_COMMIT();

    CP_WAIT(1);
    __syncthreads();

    const int arow = w * 16 + ((lane >> 3) & 1) * 8 + (lane & 7);
    const int akoff = (lane >> 4) * 8;
    uint32_t qfh[4][4], qfl[4][4];
#pragma unroll
    for (int kc = 0; kc < 4; kc++) {
        uint32_t ad = sb + A_QH + (uint32_t)arow * APITCHB + (uint32_t)(kc * 16 + akoff) * 2;
        ldsm_x4(qfh[kc], ad);
        ldsm_x4(qfl[kc], ad + (A_QL - A_QH));
    }

    float s[18][4];
#pragma unroll
    for (int t = 0; t < 18; t++)
#pragma unroll
        for (int e = 0; e < 4; e++) s[t][e] = 0.f;

    const int krow4 = (lane & 7) + ((lane >> 4) << 3);
    const int kko4  = ((lane >> 3) & 1) * 16;       // bytes
#pragma unroll
    for (int u = 0; u < 9; u++) {
        int ntb = 2 * w + 2 * u;
        uint32_t kb_addr = sb + A_KH + (uint32_t)(ntb * 8 + krow4) * APITCHB + (uint32_t)kko4;
#pragma unroll
        for (int kc = 0; kc < 4; kc++) {
            uint32_t kh4[4], kl4[4];
            uint32_t ka = kb_addr + (uint32_t)kc * 32;
            ldsm_x4(kh4, ka);
            ldsm_x4(kl4, ka + (A_KL - A_KH));
            uint32_t bh0[2] = { kh4[0], kh4[1] }, bh1[2] = { kh4[2], kh4[3] };
            uint32_t bl0[2] = { kl4[0], kl4[1] }, bl1[2] = { kl4[2], kl4[3] };
            mma_bf16(s[2 * u],     qfh[kc], bh0);
            mma_bf16(s[2 * u],     qfh[kc], bl0);
            mma_bf16(s[2 * u],     qfl[kc], bh0);
            mma_bf16(s[2 * u + 1], qfh[kc], bh1);
            mma_bf16(s[2 * u + 1], qfh[kc], bl1);
            mma_bf16(s[2 * u + 1], qfl[kc], bh1);
        }
    }

    const int g  = lane >> 2;
    const int c2 = (lane & 3) * 2;
    const int qg0 = q0 + w * 16 + g;
    const int qg1 = qg0 + 8;
    const float scale = 0.125f;

    float m0 = -1e30f, m1 = -1e30f;
#pragma unroll
    for (int t = 0; t < 18; t++) {
        int j0 = (2 * w + t) * 8 + c2;
        int kg0 = kbase + j0, kg1 = kg0 + 1;
        bool in0 = (kg0 >= 0) && (kg0 < SEQ);
        bool in1 = (kg1 >= 0) && (kg1 < SEQ);
        int d00 = kg0 - qg0, d10 = kg1 - qg0, d01 = kg0 - qg1, d11 = kg1 - qg1;
        s[t][0] = (in0 && d00 <= WIN && d00 >= -WIN) ? s[t][0] * scale : -1e30f;
        s[t][1] = (in1 && d10 <= WIN && d10 >= -WIN) ? s[t][1] * scale : -1e30f;
        s[t][2] = (in0 && d01 <= WIN && d01 >= -WIN) ? s[t][2] * scale : -1e30f;
        s[t][3] = (in1 && d11 <= WIN && d11 >= -WIN) ? s[t][3] * scale : -1e30f;
        m0 = fmaxf(m0, fmaxf(s[t][0], s[t][1]));
        m1 = fmaxf(m1, fmaxf(s[t][2], s[t][3]));
    }
    m0 = fmaxf(m0, __shfl_xor_sync(0xffffffffu, m0, 1));
    m0 = fmaxf(m0, __shfl_xor_sync(0xffffffffu, m0, 2));
    m1 = fmaxf(m1, __shfl_xor_sync(0xffffffffu, m1, 1));
    m1 = fmaxf(m1, __shfl_xor_sync(0xffffffffu, m1, 2));

    float r0 = 0.f, r1 = 0.f;
#pragma unroll
    for (int t = 0; t < 18; t++) {
        s[t][0] = __expf(s[t][0] - m0);
        s[t][1] = __expf(s[t][1] - m0);
        s[t][2] = __expf(s[t][2] - m1);
        s[t][3] = __expf(s[t][3] - m1);
        r0 += s[t][0] + s[t][1];
        r1 += s[t][2] + s[t][3];
    }
    r0 += __shfl_xor_sync(0xffffffffu, r0, 1);
    r0 += __shfl_xor_sync(0xffffffffu, r0, 2);
    r1 += __shfl_xor_sync(0xffffffffu, r1, 1);
    r1 += __shfl_xor_sync(0xffffffffu, r1, 2);
    float inv0 = 1.f / r0, inv1 = 1.f / r1;

    uint32_t ph01[18], ph23[18], pl01[18], pl23[18];
#pragma unroll
    for (int t = 0; t < 18; t++) {
        float p0 = s[t][0] * inv0, p1 = s[t][1] * inv0;
        float p2 = s[t][2] * inv1, p3 = s[t][3] * inv1;
        __nv_bfloat162 h2;
        h2.x = __float2bfloat16(p0); h2.y = __float2bfloat16(p1);
        ph01[t] = *(uint32_t*)&h2;
        pl01[t] = pack_bf2(p0 - __bfloat162float(h2.x), p1 - __bfloat162float(h2.y));
        h2.x = __float2bfloat16(p2); h2.y = __float2bfloat16(p3);
        ph23[t] = *(uint32_t*)&h2;
        pl23[t] = pack_bf2(p2 - __bfloat162float(h2.x), p3 - __bfloat162float(h2.y));
    }

    CP_WAIT(0);
    __syncthreads();

    float o[8][4];
#pragma unroll
    for (int nt = 0; nt < 8; nt++)
#pragma unroll
        for (int e = 0; e < 4; e++) o[nt][e] = 0.f;

    const int vrow_l = ((lane >> 3) & 1) * 8 + (lane & 7);
#pragma unroll
    for (int jl = 0; jl < 9; jl++) {
        uint32_t ah[4] = { ph01[2 * jl], ph23[2 * jl], ph01[2 * jl + 1], ph23[2 * jl + 1] };
        uint32_t al[4] = { pl01[2 * jl], pl23[2 * jl], pl01[2 * jl + 1], pl23[2 * jl + 1] };
        int keyb = (w + jl) * 16;
        uint32_t va_base = sb + A_VH + (uint32_t)(keyb + vrow_l) * APITCHB;
#pragma unroll
        for (int nt = 0; nt < 8; nt++) {
            uint32_t vfh[2], vfl[2];
            uint32_t va = va_base + (uint32_t)nt * 16;
            ldsm_x2t(vfh, va);
            ldsm_x2t(vfl, va + (A_VL - A_VH));
            mma_bf16(o[nt], ah, vfh);
            mma_bf16(o[nt], ah, vfl);
            mma_bf16(o[nt], al, vfh);
        }
    }

    // ---- store single fp16 for the output projection ----
    size_t row0 = tok0 + qg0;
    size_t row1 = tok0 + qg1;
#pragma unroll
    for (int nt = 0; nt < 8; nt++) {
        int col = coff + nt * 8 + c2;
        *(__half2*)(g_a16 + row0 * DMODEL + col) = __floats2half2_rn(o[nt][0], o[nt][1]);
        *(__half2*)(g_a16 + row1 * DMODEL + col) = __floats2half2_rn(o[nt][2], o[nt][3]);
    }
}

// ============================================================
extern "C" void kernel_launch(void* const* d_in, const int* in_sizes, int n_in,
                              void* d_out, int out_size)
{
    const float* x  = (const float*)d_in[0];
    const float* Wq = (const float*)d_in[1];
    const float* bq = (const float*)d_in[2];
    const float* Wk = (const float*)d_in[3];
    const float* bk = (const float*)d_in[4];
    const float* Wv = (const float*)d_in[5];
    const float* bv = (const float*)d_in[6];
    const float* Wo = (const float*)d_in[7];
    const float* bo = (const float*)d_in[8];
    float* out = (float*)d_out;

    cudaFuncSetAttribute(hmma_gemm_kernel, cudaFuncAttributeMaxDynamicSharedMemorySize, GEMM_SMEM);
    cudaFuncSetAttribute(attn_mma_kernel, cudaFuncAttributeMaxDynamicSharedMemorySize, ATTN_SMEM);

    convert_x_kernel<<<MTOT, 256>>>(x);
    transpose_w_kernel<<<dim3(32, 32, 4), dim3(32, 8)>>>(Wq, Wk, Wv, Wo);

    dim3 gq(DMODEL / 128, MTOT / 128, 3);
    hmma_gemm_kernel<<<gq, 256, GEMM_SMEM>>>(0, bq, bk, bv, nullptr);

    dim3 ga(SEQ / 128, NHEADS, BATCH);
    attn_mma_kernel<<<ga, 256, ATTN_SMEM>>>();

    dim3 go(DMODEL / 128, MTOT / 128, 1);
    hmma_gemm_kernel<<<go, 256, GEMM_SMEM>>>(1, bo, nullptr, nullptr, out);
}

// round 9
// speedup vs baseline: 2.0674x; 1.3828x over previous
#include <cuda_runtime.h>
#include <cuda_bf16.h>
#include <cuda_fp16.h>
#include <math.h>
#include <stdint.h>

#define BATCH   2
#define SEQ     2048
#define DMODEL  1024
#define NHEADS  16
#define HDIM    64
#define WIN     64
#define MTOT    (BATCH*SEQ)   // 4096
#define WSZ     (DMODEL*DMODEL)

// ---------------- scratch (static device globals) ----------------
__device__ __half g_x16[MTOT*DMODEL];          // x rounded to fp16
__device__ __half g_w16[4*WSZ];                // transposed [n][k], fp16
__device__ __nv_bfloat16 g_qh[MTOT*DMODEL];
__device__ __nv_bfloat16 g_ql[MTOT*DMODEL];
__device__ __nv_bfloat16 g_kh[MTOT*DMODEL];
__device__ __nv_bfloat16 g_kl[MTOT*DMODEL];
__device__ __nv_bfloat16 g_vh[MTOT*DMODEL];
__device__ __nv_bfloat16 g_vl[MTOT*DMODEL];
__device__ __half g_a16[MTOT*DMODEL];          // attention out, fp16

// ---------------- PTX helpers (non-'a' features only) ----------------
__device__ __forceinline__ uint32_t smem_u32(const void* p) {
    uint32_t a;
    asm("{ .reg .u64 t; cvta.to.shared.u64 t, %1; cvt.u32.u64 %0, t; }" : "=r"(a) : "l"(p));
    return a;
}
__device__ __forceinline__ void cp_async16(uint32_t s, const void* g) {
    asm volatile("cp.async.cg.shared.global [%0], [%1], 16;" :: "r"(s), "l"(g));
}
__device__ __forceinline__ void cp_async16z(uint32_t s, const void* g, uint32_t srcsz) {
    asm volatile("cp.async.cg.shared.global [%0], [%1], 16, %2;" :: "r"(s), "l"(g), "r"(srcsz));
}
#define CP_COMMIT() asm volatile("cp.async.commit_group;" ::: "memory")
#define CP_WAIT(n)  asm volatile("cp.async.wait_group %0;" :: "n"(n) : "memory")

__device__ __forceinline__ void ldsm_x4(uint32_t* r, uint32_t a) {
    asm volatile("ldmatrix.sync.aligned.m8n8.x4.shared.b16 {%0,%1,%2,%3}, [%4];"
        : "=r"(r[0]), "=r"(r[1]), "=r"(r[2]), "=r"(r[3]) : "r"(a));
}
__device__ __forceinline__ void ldsm_x2(uint32_t* r, uint32_t a) {
    asm volatile("ldmatrix.sync.aligned.m8n8.x2.shared.b16 {%0,%1}, [%2];"
        : "=r"(r[0]), "=r"(r[1]) : "r"(a));
}
__device__ __forceinline__ void ldsm_x2t(uint32_t* r, uint32_t a) {
    asm volatile("ldmatrix.sync.aligned.m8n8.x2.trans.shared.b16 {%0,%1}, [%2];"
        : "=r"(r[0]), "=r"(r[1]) : "r"(a));
}
__device__ __forceinline__ void mma_bf16(float* d, const uint32_t* a, const uint32_t* b) {
    asm volatile(
        "mma.sync.aligned.m16n8k16.row.col.f32.bf16.bf16.f32 "
        "{%0,%1,%2,%3}, {%4,%5,%6,%7}, {%8,%9}, {%0,%1,%2,%3};"
        : "+f"(d[0]), "+f"(d[1]), "+f"(d[2]), "+f"(d[3])
        : "r"(a[0]), "r"(a[1]), "r"(a[2]), "r"(a[3]), "r"(b[0]), "r"(b[1]));
}
__device__ __forceinline__ void mma_f16(float* d, const uint32_t* a, const uint32_t* b) {
    asm volatile(
        "mma.sync.aligned.m16n8k16.row.col.f32.f16.f16.f32 "
        "{%0,%1,%2,%3}, {%4,%5,%6,%7}, {%8,%9}, {%0,%1,%2,%3};"
        : "+f"(d[0]), "+f"(d[1]), "+f"(d[2]), "+f"(d[3])
        : "r"(a[0]), "r"(a[1]), "r"(a[2]), "r"(a[3]), "r"(b[0]), "r"(b[1]));
}

__device__ __forceinline__ uint32_t pack_bf2(float x, float y) {
    __nv_bfloat162 h;
    h.x = __float2bfloat16(x); h.y = __float2bfloat16(y);
    return *(uint32_t*)&h;
}

// ============================================================
// Conversion kernels
// ============================================================
__global__ __launch_bounds__(256) void convert_x_kernel(const float* __restrict__ x)
{
    size_t off = (size_t)blockIdx.x * DMODEL + threadIdx.x * 4;
    float4 v = *(const float4*)(x + off);
    *(__half2*)(g_x16 + off)     = __floats2half2_rn(v.x, v.y);
    *(__half2*)(g_x16 + off + 2) = __floats2half2_rn(v.z, v.w);
}

// transpose W[k][n] -> Wt[n][k], fp16. block (32,8), tile 32x32
__global__ __launch_bounds__(256) void transpose_w_kernel(
    const float* __restrict__ Wq, const float* __restrict__ Wk,
    const float* __restrict__ Wv, const float* __restrict__ Wo)
{
    __shared__ float tile[32][33];
    int z = blockIdx.z;
    const float* W = (z == 0) ? Wq : (z == 1) ? Wk : (z == 2) ? Wv : Wo;
    __half* T = g_w16 + (size_t)z * WSZ;
    int kb = blockIdx.y * 32, nb = blockIdx.x * 32;
    int tx = threadIdx.x, ty = threadIdx.y;
#pragma unroll
    for (int i = 0; i < 4; i++)
        tile[ty + 8 * i][tx] = W[(size_t)(kb + ty + 8 * i) * DMODEL + nb + tx];
    __syncthreads();
#pragma unroll
    for (int i = 0; i < 4; i++) {
        T[(size_t)(nb + ty + 8 * i) * DMODEL + kb + tx] =
            __float2half_rn(tile[tx][ty + 8 * i]);
    }
}

// ============================================================
// Single-pass fp16 HMMA GEMM: C = A16 @ W16^T + bias
// CTA tile 128x128, BK=32, 8 warps (2x4), warp tile 64x32.
// 3-stage cp.async, stage = A(10240) + B(10240) = 20480 B -> 2 CTAs/SM.
// ============================================================
#define BK       32
#define PITCHB   80                    // bytes per SMEM row (40 fp16)
#define MAT_B    (128*PITCHB)          // 10240 B per matrix tile
#define STAGE_B2 (2*MAT_B)             // 20480 B per stage
#define NSTAGE   3
#define GEMM_SMEM (NSTAGE*STAGE_B2)    // 61440 B
#define ROW64B   (64*PITCHB)

__global__ __launch_bounds__(256) void hmma_gemm_kernel(
    int mode, const float* __restrict__ b0, const float* __restrict__ b1,
    const float* __restrict__ b2, float* __restrict__ outp)
{
    extern __shared__ char sm[];
    const uint32_t sbase = smem_u32(sm);

    const int tid  = threadIdx.x;
    const int lane = tid & 31;
    const int wid  = tid >> 5;
    const int wm   = wid >> 2;
    const int wn   = wid & 3;
    const int m0   = blockIdx.y * 128;
    const int n0   = blockIdx.x * 128;
    const int z    = blockIdx.z;

    const __half *A, *B;
    const float* bias;
    if (mode == 0) {
        A = g_x16;
        B = g_w16 + (size_t)z * WSZ;
        bias = (z == 0) ? b0 : (z == 1) ? b1 : b2;
    } else {
        A = g_a16;
        B = g_w16 + 3ull * WSZ;
        bias = b0;
    }

    const int rowA = tid >> 2;
    const int seg  = tid & 3;
    const uint32_t s0 = (uint32_t)rowA * PITCHB + (uint32_t)seg * 16;
    const __half* pA = A + (size_t)(m0 + rowA) * DMODEL + seg * 8;
    const __half* pB = B + (size_t)(n0 + rowA) * DMODEL + seg * 8;

#define PREFETCH(stage, cc) do {                                             \
    const int _k0 = (cc) * BK;                                               \
    const uint32_t _sb = sbase + (uint32_t)(stage) * STAGE_B2 + s0;          \
    cp_async16(_sb,                  pA + _k0);                              \
    cp_async16(_sb + ROW64B,         pA + 64 * DMODEL + _k0);                \
    cp_async16(_sb + MAT_B,          pB + _k0);                              \
    cp_async16(_sb + MAT_B + ROW64B, pB + 64 * DMODEL + _k0);                \
} while (0)

    float acc[4][4][4];
#pragma unroll
    for (int i = 0; i < 4; i++)
#pragma unroll
        for (int j = 0; j < 4; j++)
#pragma unroll
            for (int e = 0; e < 4; e++) acc[i][j][e] = 0.f;

    const int arow_l = ((lane >> 3) & 1) * 8 + (lane & 7);
    const int akoff  = (lane >> 4) * 8;
    const int brow_l = lane & 7;
    const int bkoff  = ((lane >> 3) & 1) * 8;

    PREFETCH(0, 0); CP_COMMIT();
    PREFETCH(1, 1); CP_COMMIT();

    const int NCHUNK = DMODEL / BK;   // 32
    int scur = 0, spre = 2;
    for (int c = 0; c < NCHUNK; c++) {
        if (c + 2 < NCHUNK)      { PREFETCH(spre, c + 2); CP_COMMIT(); CP_WAIT(2); }
        else if (c + 1 < NCHUNK) { CP_WAIT(1); }
        else                     { CP_WAIT(0); }
        __syncthreads();

        const uint32_t stb = sbase + (uint32_t)scur * STAGE_B2;
#pragma unroll
        for (int ks = 0; ks < 2; ks++) {
            uint32_t a[4][4], bfr[4][2];
#pragma unroll
            for (int mt = 0; mt < 4; mt++) {
                uint32_t ad = stb + (uint32_t)(wm * 64 + mt * 16 + arow_l) * PITCHB
                                  + (uint32_t)(ks * 16 + akoff) * 2;
                ldsm_x4(a[mt], ad);
            }
#pragma unroll
            for (int nt = 0; nt < 4; nt++) {
                uint32_t bd = stb + MAT_B
                                  + (uint32_t)(wn * 32 + nt * 8 + brow_l) * PITCHB
                                  + (uint32_t)(ks * 16 + bkoff) * 2;
                ldsm_x2(bfr[nt], bd);
            }
#pragma unroll
            for (int mt = 0; mt < 4; mt++)
#pragma unroll
                for (int nt = 0; nt < 4; nt++)
                    mma_f16(acc[mt][nt], a[mt], bfr[nt]);
        }
        __syncthreads();
        scur = (scur == 2) ? 0 : scur + 1;
        spre = (spre == 2) ? 0 : spre + 1;
    }

    const int g     = lane >> 2;
    const int cpair = (lane & 3) * 2;
    if (mode == 0) {
        __nv_bfloat16* Ch = (z == 0) ? g_qh : (z == 1) ? g_kh : g_vh;
        __nv_bfloat16* Cl = (z == 0) ? g_ql : (z == 1) ? g_kl : g_vl;
#pragma unroll
        for (int mt = 0; mt < 4; mt++) {
            int row0 = m0 + wm * 64 + mt * 16 + g;
#pragma unroll
            for (int nt = 0; nt < 4; nt++) {
                int col = n0 + wn * 32 + nt * 8 + cpair;
                float bx = bias[col], by = bias[col + 1];
#pragma unroll
                for (int rr = 0; rr < 2; rr++) {
                    float o0 = acc[mt][nt][rr * 2 + 0] + bx;
                    float o1 = acc[mt][nt][rr * 2 + 1] + by;
                    __nv_bfloat162 h2, l2;
                    h2.x = __float2bfloat16(o0); l2.x = __float2bfloat16(o0 - __bfloat162float(h2.x));
                    h2.y = __float2bfloat16(o1); l2.y = __float2bfloat16(o1 - __bfloat162float(h2.y));
                    size_t off = (size_t)(row0 + rr * 8) * DMODEL + col;
                    *(__nv_bfloat162*)(Ch + off) = h2;
                    *(__nv_bfloat162*)(Cl + off) = l2;
                }
            }
        }
    } else {
        float* C = outp;
#pragma unroll
        for (int mt = 0; mt < 4; mt++) {
            int row0 = m0 + wm * 64 + mt * 16 + g;
#pragma unroll
            for (int nt = 0; nt < 4; nt++) {
                int col = n0 + wn * 32 + nt * 8 + cpair;
                float bx = bias[col], by = bias[col + 1];
                *(float2*)(C + (size_t)row0 * DMODEL + col) =
                    make_float2(acc[mt][nt][0] + bx, acc[mt][nt][1] + by);
                *(float2*)(C + (size_t)(row0 + 8) * DMODEL + col) =
                    make_float2(acc[mt][nt][2] + bx, acc[mt][nt][3] + by);
            }
        }
    }
#undef PREFETCH
}

// ============================================================
// Banded flash-attention with mma.sync (split bf16 hi/lo)
// CTA = (128 queries, head, batch); 8 warps; warp = 16 query rows.
// ============================================================
#define APITCHB  144
#define A_QH     0
#define A_QL     18432              // 128*144
#define A_KH     36864
#define A_KL     73728              // +256*144
#define A_VH     110592
#define A_VL     147456
#define ATTN_SMEM 184320

__global__ __launch_bounds__(256) void attn_mma_kernel()
{
    extern __shared__ char sm[];
    const uint32_t sb = smem_u32(sm);

    const int tid  = threadIdx.x;
    const int lane = tid & 31;
    const int w    = tid >> 5;          // 0..7
    const int b    = blockIdx.z;
    const int h    = blockIdx.y;
    const int q0   = blockIdx.x * 128;
    const int kbase = q0 - WIN;
    const size_t tok0 = (size_t)b * SEQ;
    const int coff = h * HDIM;

#pragma unroll
    for (int i = 0; i < 4; i++) {
        int task = tid + i * 256;
        int row = task >> 3, seg = task & 7;
        uint32_t d = sb + A_QH + (uint32_t)row * APITCHB + (uint32_t)seg * 16;
        size_t goff = (tok0 + q0 + row) * DMODEL + coff + seg * 8;
        cp_async16(d,                 g_qh + goff);
        cp_async16(d + (A_QL - A_QH), g_ql + goff);
    }
#pragma unroll
    for (int i = 0; i < 8; i++) {
        int task = tid + i * 256;
        int row = task >> 3, seg = task & 7;
        int kg = kbase + row;
        int kgc = min(max(kg, 0), SEQ - 1);
        uint32_t sz = (kg >= 0 && kg < SEQ) ? 16u : 0u;
        uint32_t d = sb + A_KH + (uint32_t)row * APITCHB + (uint32_t)seg * 16;
        size_t goff = (tok0 + kgc) * DMODEL + coff + seg * 8;
        cp_async16z(d,                 g_kh + goff, sz);
        cp_async16z(d + (A_KL - A_KH), g_kl + goff, sz);
    }
    CP_COMMIT();
#pragma unroll
    for (int i = 0; i < 8; i++) {
        int task = tid + i * 256;
        int row = task >> 3, seg = task & 7;
        int kg = kbase + row;
        int kgc = min(max(kg, 0), SEQ - 1);
        uint32_t sz = (kg >= 0 && kg < SEQ) ? 16u : 0u;
        uint32_t d = sb + A_VH + (uint32_t)row * APITCHB + (uint32_t)seg * 16;
        size_t goff = (tok0 + kgc) * DMODEL + coff + seg * 8;
        cp_async16z(d,                 g_vh + goff, sz);
        cp_async16z(d + (A_VL - A_VH), g_vl + goff, sz);
    }
    CP_COMMIT();

    CP_WAIT(1);
    __syncthreads();

    const int arow = w * 16 + ((lane >> 3) & 1) * 8 + (lane & 7);
    const int akoff = (lane >> 4) * 8;
    uint32_t qfh[4][4], qfl[4][4];
#pragma unroll
    for (int kc = 0; kc < 4; kc++) {
        uint32_t ad = sb + A_QH + (uint32_t)arow * APITCHB + (uint32_t)(kc * 16 + akoff) * 2;
        ldsm_x4(qfh[kc], ad);
        ldsm_x4(qfl[kc], ad + (A_QL - A_QH));
    }

    float s[18][4];
#pragma unroll
    for (int t = 0; t < 18; t++)
#pragma unroll
        for (int e = 0; e < 4; e++) s[t][e] = 0.f;

    const int krow4 = (lane & 7) + ((lane >> 4) << 3);
    const int kko4  = ((lane >> 3) & 1) * 16;       // bytes
#pragma unroll
    for (int u = 0; u < 9; u++) {
        int ntb = 2 * w + 2 * u;
        uint32_t kb_addr = sb + A_KH + (uint32_t)(ntb * 8 + krow4) * APITCHB + (uint32_t)kko4;
#pragma unroll
        for (int kc = 0; kc < 4; kc++) {
            uint32_t kh4[4], kl4[4];
            uint32_t ka = kb_addr + (uint32_t)kc * 32;
            ldsm_x4(kh4, ka);
            ldsm_x4(kl4, ka + (A_KL - A_KH));
            uint32_t bh0[2] = { kh4[0], kh4[1] }, bh1[2] = { kh4[2], kh4[3] };
            uint32_t bl0[2] = { kl4[0], kl4[1] }, bl1[2] = { kl4[2], kl4[3] };
            mma_bf16(s[2 * u],     qfh[kc], bh0);
            mma_bf16(s[2 * u],     qfh[kc], bl0);
            mma_bf16(s[2 * u],     qfl[kc], bh0);
            mma_bf16(s[2 * u + 1], qfh[kc], bh1);
            mma_bf16(s[2 * u + 1], qfh[kc], bl1);
            mma_bf16(s[2 * u + 1], qfl[kc], bh1);
        }
    }

    const int g  = lane >> 2;
    const int c2 = (lane & 3) * 2;
    const int qg0 = q0 + w * 16 + g;
    const int qg1 = qg0 + 8;
    const float scale = 0.125f;

    float m0 = -1e30f, m1 = -1e30f;
#pragma unroll
    for (int t = 0; t < 18; t++) {
        int j0 = (2 * w + t) * 8 + c2;
        int kg0 = kbase + j0, kg1 = kg0 + 1;
        bool in0 = (kg0 >= 0) && (kg0 < SEQ);
        bool in1 = (kg1 >= 0) && (kg1 < SEQ);
        int d00 = kg0 - qg0, d10 = kg1 - qg0, d01 = kg0 - qg1, d11 = kg1 - qg1;
        s[t][0] = (in0 && d00 <= WIN && d00 >= -WIN) ? s[t][0] * scale : -1e30f;
        s[t][1] = (in1 && d10 <= WIN && d10 >= -WIN) ? s[t][1] * scale : -1e30f;
        s[t][2] = (in0 && d01 <= WIN && d01 >= -WIN) ? s[t][2] * scale : -1e30f;
        s[t][3] = (in1 && d11 <= WIN && d11 >= -WIN) ? s[t][3] * scale : -1e30f;
        m0 = fmaxf(m0, fmaxf(s[t][0], s[t][1]));
        m1 = fmaxf(m1, fmaxf(s[t][2], s[t][3]));
    }
    m0 = fmaxf(m0, __shfl_xor_sync(0xffffffffu, m0, 1));
    m0 = fmaxf(m0, __shfl_xor_sync(0xffffffffu, m0, 2));
    m1 = fmaxf(m1, __shfl_xor_sync(0xffffffffu, m1, 1));
    m1 = fmaxf(m1, __shfl_xor_sync(0xffffffffu, m1, 2));

    float r0 = 0.f, r1 = 0.f;
#pragma unroll
    for (int t = 0; t < 18; t++) {
        s[t][0] = __expf(s[t][0] - m0);
        s[t][1] = __expf(s[t][1] - m0);
        s[t][2] = __expf(s[t][2] - m1);
        s[t][3] = __expf(s[t][3] - m1);
        r0 += s[t][0] + s[t][1];
        r1 += s[t][2] + s[t][3];
    }
    r0 += __shfl_xor_sync(0xffffffffu, r0, 1);
    r0 += __shfl_xor_sync(0xffffffffu, r0, 2);
    r1 += __shfl_xor_sync(0xffffffffu, r1, 1);
    r1 += __shfl_xor_sync(0xffffffffu, r1, 2);
    float inv0 = 1.f / r0, inv1 = 1.f / r1;

    uint32_t ph01[18], ph23[18], pl01[18], pl23[18];
#pragma unroll
    for (int t = 0; t < 18; t++) {
        float p0 = s[t][0] * inv0, p1 = s[t][1] * inv0;
        float p2 = s[t][2] * inv1, p3 = s[t][3] * inv1;
        __nv_bfloat162 h2;
        h2.x = __float2bfloat16(p0); h2.y = __float2bfloat16(p1);
        ph01[t] = *(uint32_t*)&h2;
        pl01[t] = pack_bf2(p0 - __bfloat162float(h2.x), p1 - __bfloat162float(h2.y));
        h2.x = __float2bfloat16(p2); h2.y = __float2bfloat16(p3);
        ph23[t] = *(uint32_t*)&h2;
        pl23[t] = pack_bf2(p2 - __bfloat162float(h2.x), p3 - __bfloat162float(h2.y));
    }

    CP_WAIT(0);
    __syncthreads();

    float o[8][4];
#pragma unroll
    for (int nt = 0; nt < 8; nt++)
#pragma unroll
        for (int e = 0; e < 4; e++) o[nt][e] = 0.f;

    const int vrow_l = ((lane >> 3) & 1) * 8 + (lane & 7);
#pragma unroll
    for (int jl = 0; jl < 9; jl++) {
        uint32_t ah[4] = { ph01[2 * jl], ph23[2 * jl], ph01[2 * jl + 1], ph23[2 * jl + 1] };
        uint32_t al[4] = { pl01[2 * jl], pl23[2 * jl], pl01[2 * jl + 1], pl23[2 * jl + 1] };
        int keyb = (w + jl) * 16;
        uint32_t va_base = sb + A_VH + (uint32_t)(keyb + vrow_l) * APITCHB;
#pragma unroll
        for (int nt = 0; nt < 8; nt++) {
            uint32_t vfh[2], vfl[2];
            uint32_t va = va_base + (uint32_t)nt * 16;
            ldsm_x2t(vfh, va);
            ldsm_x2t(vfl, va + (A_VL - A_VH));
            mma_bf16(o[nt], ah, vfh);
            mma_bf16(o[nt], ah, vfl);
            mma_bf16(o[nt], al, vfh);
        }
    }

    size_t row0 = tok0 + qg0;
    size_t row1 = tok0 + qg1;
#pragma unroll
    for (int nt = 0; nt < 8; nt++) {
        int col = coff + nt * 8 + c2;
        *(__half2*)(g_a16 + row0 * DMODEL + col) = __floats2half2_rn(o[nt][0], o[nt][1]);
        *(__half2*)(g_a16 + row1 * DMODEL + col) = __floats2half2_rn(o[nt][2], o[nt][3]);
    }
}

// ============================================================
extern "C" void kernel_launch(void* const* d_in, const int* in_sizes, int n_in,
                              void* d_out, int out_size)
{
    const float* x  = (const float*)d_in[0];
    const float* Wq = (const float*)d_in[1];
    const float* bq = (const float*)d_in[2];
    const float* Wk = (const float*)d_in[3];
    const float* bk = (const float*)d_in[4];
    const float* Wv = (const float*)d_in[5];
    const float* bv = (const float*)d_in[6];
    const float* Wo = (const float*)d_in[7];
    const float* bo = (const float*)d_in[8];
    float* out = (float*)d_out;

    cudaFuncSetAttribute(hmma_gemm_kernel, cudaFuncAttributeMaxDynamicSharedMemorySize, GEMM_SMEM);
    cudaFuncSetAttribute(attn_mma_kernel, cudaFuncAttributeMaxDynamicSharedMemorySize, ATTN_SMEM);

    convert_x_kernel<<<MTOT, 256>>>(x);
    transpose_w_kernel<<<dim3(32, 32, 4), dim3(32, 8)>>>(Wq, Wk, Wv, Wo);

    dim3 gq(DMODEL / 128, MTOT / 128, 3);
    hmma_gemm_kernel<<<gq, 256, GEMM_SMEM>>>(0, bq, bk, bv, nullptr);

    dim3 ga(SEQ / 128, NHEADS, BATCH);
    attn_mma_kernel<<<ga, 256, ATTN_SMEM>>>();

    dim3 go(DMODEL / 128, MTOT / 128, 1);
    hmma_gemm_kernel<<<go, 256, GEMM_SMEM>>>(1, bo, nullptr, nullptr, out);
}

// round 10
// speedup vs baseline: 2.3260x; 1.1251x over previous
#include <cuda_runtime.h>
#include <cuda_bf16.h>
#include <cuda_fp16.h>
#include <math.h>
#include <stdint.h>

#define BATCH   2
#define SEQ     2048
#define DMODEL  1024
#define NHEADS  16
#define HDIM    64
#define WIN     64
#define MTOT    (BATCH*SEQ)   // 4096
#define WSZ     (DMODEL*DMODEL)

// ---------------- scratch (static device globals) ----------------
__device__ __half g_x16[MTOT*DMODEL];          // x rounded to fp16
__device__ __half g_w16[4*WSZ];                // transposed [n][k], fp16
__device__ __half g_q16[MTOT*DMODEL];
__device__ __half g_k16[MTOT*DMODEL];
__device__ __half g_v16[MTOT*DMODEL];
__device__ __half g_a16[MTOT*DMODEL];          // attention out, fp16

// ---------------- PTX helpers (non-'a' features only) ----------------
__device__ __forceinline__ uint32_t smem_u32(const void* p) {
    uint32_t a;
    asm("{ .reg .u64 t; cvta.to.shared.u64 t, %1; cvt.u32.u64 %0, t; }" : "=r"(a) : "l"(p));
    return a;
}
__device__ __forceinline__ void cp_async16(uint32_t s, const void* g) {
    asm volatile("cp.async.cg.shared.global [%0], [%1], 16;" :: "r"(s), "l"(g));
}
__device__ __forceinline__ void cp_async16z(uint32_t s, const void* g, uint32_t srcsz) {
    asm volatile("cp.async.cg.shared.global [%0], [%1], 16, %2;" :: "r"(s), "l"(g), "r"(srcsz));
}
#define CP_COMMIT() asm volatile("cp.async.commit_group;" ::: "memory")
#define CP_WAIT(n)  asm volatile("cp.async.wait_group %0;" :: "n"(n) : "memory")

__device__ __forceinline__ void ldsm_x4(uint32_t* r, uint32_t a) {
    asm volatile("ldmatrix.sync.aligned.m8n8.x4.shared.b16 {%0,%1,%2,%3}, [%4];"
        : "=r"(r[0]), "=r"(r[1]), "=r"(r[2]), "=r"(r[3]) : "r"(a));
}
__device__ __forceinline__ void ldsm_x2(uint32_t* r, uint32_t a) {
    asm volatile("ldmatrix.sync.aligned.m8n8.x2.shared.b16 {%0,%1}, [%2];"
        : "=r"(r[0]), "=r"(r[1]) : "r"(a));
}
__device__ __forceinline__ void ldsm_x2t(uint32_t* r, uint32_t a) {
    asm volatile("ldmatrix.sync.aligned.m8n8.x2.trans.shared.b16 {%0,%1}, [%2];"
        : "=r"(r[0]), "=r"(r[1]) : "r"(a));
}
__device__ __forceinline__ void mma_f16(float* d, const uint32_t* a, const uint32_t* b) {
    asm volatile(
        "mma.sync.aligned.m16n8k16.row.col.f32.f16.f16.f32 "
        "{%0,%1,%2,%3}, {%4,%5,%6,%7}, {%8,%9}, {%0,%1,%2,%3};"
        : "+f"(d[0]), "+f"(d[1]), "+f"(d[2]), "+f"(d[3])
        : "r"(a[0]), "r"(a[1]), "r"(a[2]), "r"(a[3]), "r"(b[0]), "r"(b[1]));
}

__device__ __forceinline__ uint32_t pack_hf2(float x, float y) {
    __half2 h = __floats2half2_rn(x, y);
    return *(uint32_t*)&h;
}

// ============================================================
// Conversion kernels
// ============================================================
__global__ __launch_bounds__(256) void convert_x_kernel(const float* __restrict__ x)
{
    size_t off = (size_t)blockIdx.x * DMODEL + threadIdx.x * 4;
    float4 v = *(const float4*)(x + off);
    *(__half2*)(g_x16 + off)     = __floats2half2_rn(v.x, v.y);
    *(__half2*)(g_x16 + off + 2) = __floats2half2_rn(v.z, v.w);
}

// transpose W[k][n] -> Wt[n][k], fp16. block (32,8), tile 32x32
__global__ __launch_bounds__(256) void transpose_w_kernel(
    const float* __restrict__ Wq, const float* __restrict__ Wk,
    const float* __restrict__ Wv, const float* __restrict__ Wo)
{
    __shared__ float tile[32][33];
    int z = blockIdx.z;
    const float* W = (z == 0) ? Wq : (z == 1) ? Wk : (z == 2) ? Wv : Wo;
    __half* T = g_w16 + (size_t)z * WSZ;
    int kb = blockIdx.y * 32, nb = blockIdx.x * 32;
    int tx = threadIdx.x, ty = threadIdx.y;
#pragma unroll
    for (int i = 0; i < 4; i++)
        tile[ty + 8 * i][tx] = W[(size_t)(kb + ty + 8 * i) * DMODEL + nb + tx];
    __syncthreads();
#pragma unroll
    for (int i = 0; i < 4; i++) {
        T[(size_t)(nb + ty + 8 * i) * DMODEL + kb + tx] =
            __float2half_rn(tile[tx][ty + 8 * i]);
    }
}

// ============================================================
// Single-pass fp16 HMMA GEMM: C = A16 @ W16^T + bias
// CTA tile 128x128, BK=32, 8 warps (2x4), warp tile 64x32.
// 3-stage cp.async, stage = 20480 B -> 2 CTAs/SM.
// ============================================================
#define BK       32
#define PITCHB   80                    // bytes per SMEM row (40 fp16)
#define MAT_B    (128*PITCHB)          // 10240 B per matrix tile
#define STAGE_B2 (2*MAT_B)             // 20480 B per stage
#define NSTAGE   3
#define GEMM_SMEM (NSTAGE*STAGE_B2)    // 61440 B
#define ROW64B   (64*PITCHB)

__global__ __launch_bounds__(256) void hmma_gemm_kernel(
    int mode, const float* __restrict__ b0, const float* __restrict__ b1,
    const float* __restrict__ b2, float* __restrict__ outp)
{
    extern __shared__ char sm[];
    const uint32_t sbase = smem_u32(sm);

    const int tid  = threadIdx.x;
    const int lane = tid & 31;
    const int wid  = tid >> 5;
    const int wm   = wid >> 2;
    const int wn   = wid & 3;
    const int m0   = blockIdx.y * 128;
    const int n0   = blockIdx.x * 128;
    const int z    = blockIdx.z;

    const __half *A, *B;
    const float* bias;
    if (mode == 0) {
        A = g_x16;
        B = g_w16 + (size_t)z * WSZ;
        bias = (z == 0) ? b0 : (z == 1) ? b1 : b2;
    } else {
        A = g_a16;
        B = g_w16 + 3ull * WSZ;
        bias = b0;
    }

    const int rowA = tid >> 2;
    const int seg  = tid & 3;
    const uint32_t s0 = (uint32_t)rowA * PITCHB + (uint32_t)seg * 16;
    const __half* pA = A + (size_t)(m0 + rowA) * DMODEL + seg * 8;
    const __half* pB = B + (size_t)(n0 + rowA) * DMODEL + seg * 8;

#define PREFETCH(stage, cc) do {                                             \
    const int _k0 = (cc) * BK;                                               \
    const uint32_t _sb = sbase + (uint32_t)(stage) * STAGE_B2 + s0;          \
    cp_async16(_sb,                  pA + _k0);                              \
    cp_async16(_sb + ROW64B,         pA + 64 * DMODEL + _k0);                \
    cp_async16(_sb + MAT_B,          pB + _k0);                              \
    cp_async16(_sb + MAT_B + ROW64B, pB + 64 * DMODEL + _k0);                \
} while (0)

    float acc[4][4][4];
#pragma unroll
    for (int i = 0; i < 4; i++)
#pragma unroll
        for (int j = 0; j < 4; j++)
#pragma unroll
            for (int e = 0; e < 4; e++) acc[i][j][e] = 0.f;

    const int arow_l = ((lane >> 3) & 1) * 8 + (lane & 7);
    const int akoff  = (lane >> 4) * 8;
    const int brow_l = lane & 7;
    const int bkoff  = ((lane >> 3) & 1) * 8;

    PREFETCH(0, 0); CP_COMMIT();
    PREFETCH(1, 1); CP_COMMIT();

    const int NCHUNK = DMODEL / BK;   // 32
    int scur = 0, spre = 2;
    for (int c = 0; c < NCHUNK; c++) {
        if (c + 2 < NCHUNK)      { PREFETCH(spre, c + 2); CP_COMMIT(); CP_WAIT(2); }
        else if (c + 1 < NCHUNK) { CP_WAIT(1); }
        else                     { CP_WAIT(0); }
        __syncthreads();

        const uint32_t stb = sbase + (uint32_t)scur * STAGE_B2;
#pragma unroll
        for (int ks = 0; ks < 2; ks++) {
            uint32_t a[4][4], bfr[4][2];
#pragma unroll
            for (int mt = 0; mt < 4; mt++) {
                uint32_t ad = stb + (uint32_t)(wm * 64 + mt * 16 + arow_l) * PITCHB
                                  + (uint32_t)(ks * 16 + akoff) * 2;
                ldsm_x4(a[mt], ad);
            }
#pragma unroll
            for (int nt = 0; nt < 4; nt++) {
                uint32_t bd = stb + MAT_B
                                  + (uint32_t)(wn * 32 + nt * 8 + brow_l) * PITCHB
                                  + (uint32_t)(ks * 16 + bkoff) * 2;
                ldsm_x2(bfr[nt], bd);
            }
#pragma unroll
            for (int mt = 0; mt < 4; mt++)
#pragma unroll
                for (int nt = 0; nt < 4; nt++)
                    mma_f16(acc[mt][nt], a[mt], bfr[nt]);
        }
        __syncthreads();
        scur = (scur == 2) ? 0 : scur + 1;
        spre = (spre == 2) ? 0 : spre + 1;
    }

    const int g     = lane >> 2;
    const int cpair = (lane & 3) * 2;
    if (mode == 0) {
        __half* C16 = (z == 0) ? g_q16 : (z == 1) ? g_k16 : g_v16;
#pragma unroll
        for (int mt = 0; mt < 4; mt++) {
            int row0 = m0 + wm * 64 + mt * 16 + g;
#pragma unroll
            for (int nt = 0; nt < 4; nt++) {
                int col = n0 + wn * 32 + nt * 8 + cpair;
                float bx = bias[col], by = bias[col + 1];
#pragma unroll
                for (int rr = 0; rr < 2; rr++) {
                    size_t off = (size_t)(row0 + rr * 8) * DMODEL + col;
                    *(__half2*)(C16 + off) =
                        __floats2half2_rn(acc[mt][nt][rr * 2 + 0] + bx,
                                          acc[mt][nt][rr * 2 + 1] + by);
                }
            }
        }
    } else {
        float* C = outp;
#pragma unroll
        for (int mt = 0; mt < 4; mt++) {
            int row0 = m0 + wm * 64 + mt * 16 + g;
#pragma unroll
            for (int nt = 0; nt < 4; nt++) {
                int col = n0 + wn * 32 + nt * 8 + cpair;
                float bx = bias[col], by = bias[col + 1];
                *(float2*)(C + (size_t)row0 * DMODEL + col) =
                    make_float2(acc[mt][nt][0] + bx, acc[mt][nt][1] + by);
                *(float2*)(C + (size_t)(row0 + 8) * DMODEL + col) =
                    make_float2(acc[mt][nt][2] + bx, acc[mt][nt][3] + by);
            }
        }
    }
#undef PREFETCH
}

// ============================================================
// Banded flash-attention, single fp16 Q/K/V, split-fp16 P.
// CTA = (128 queries, head, batch); 8 warps; warp = 16 query rows.
// smem: Q 128x72h, K 256x72h, V 256x72h = 92160 B -> 2 CTAs/SM.
// ============================================================
#define APITCHB  144
#define A_Q      0
#define A_K      18432              // 128*144
#define A_V      55296              // +256*144
#define ATTN_SMEM 92160

__global__ __launch_bounds__(256, 2) void attn_mma_kernel()
{
    extern __shared__ char sm[];
    const uint32_t sb = smem_u32(sm);

    const int tid  = threadIdx.x;
    const int lane = tid & 31;
    const int w    = tid >> 5;          // 0..7
    const int b    = blockIdx.z;
    const int h    = blockIdx.y;
    const int q0   = blockIdx.x * 128;
    const int kbase = q0 - WIN;
    const size_t tok0 = (size_t)b * SEQ;
    const int coff = h * HDIM;

    // ---- group 0: Q (128 rows) + K (256 rows); group 1: V (256 rows) ----
#pragma unroll
    for (int i = 0; i < 4; i++) {
        int task = tid + i * 256;          // 1024 tasks
        int row = task >> 3, seg = task & 7;
        uint32_t d = sb + A_Q + (uint32_t)row * APITCHB + (uint32_t)seg * 16;
        cp_async16(d, g_q16 + (tok0 + q0 + row) * DMODEL + coff + seg * 8);
    }
#pragma unroll
    for (int i = 0; i < 8; i++) {
        int task = tid + i * 256;          // 2048 tasks
        int row = task >> 3, seg = task & 7;
        int kg = kbase + row;
        int kgc = min(max(kg, 0), SEQ - 1);
        uint32_t sz = (kg >= 0 && kg < SEQ) ? 16u : 0u;
        uint32_t d = sb + A_K + (uint32_t)row * APITCHB + (uint32_t)seg * 16;
        cp_async16z(d, g_k16 + (tok0 + kgc) * DMODEL + coff + seg * 8, sz);
    }
    CP_COMMIT();
#pragma unroll
    for (int i = 0; i < 8; i++) {
        int task = tid + i * 256;
        int row = task >> 3, seg = task & 7;
        int kg = kbase + row;
        int kgc = min(max(kg, 0), SEQ - 1);
        uint32_t sz = (kg >= 0 && kg < SEQ) ? 16u : 0u;
        uint32_t d = sb + A_V + (uint32_t)row * APITCHB + (uint32_t)seg * 16;
        cp_async16z(d, g_v16 + (tok0 + kgc) * DMODEL + coff + seg * 8, sz);
    }
    CP_COMMIT();

    CP_WAIT(1);
    __syncthreads();

    // ---- Q fragments ----
    const int arow = w * 16 + ((lane >> 3) & 1) * 8 + (lane & 7);
    const int akoff = (lane >> 4) * 8;
    uint32_t qf[4][4];
#pragma unroll
    for (int kc = 0; kc < 4; kc++) {
        uint32_t ad = sb + A_Q + (uint32_t)arow * APITCHB + (uint32_t)(kc * 16 + akoff) * 2;
        ldsm_x4(qf[kc], ad);
    }

    // ---- QK: S[16][144], 18 n-tiles as 9 pairs via ldsm_x4, 1 pass ----
    float s[18][4];
#pragma unroll
    for (int t = 0; t < 18; t++)
#pragma unroll
        for (int e = 0; e < 4; e++) s[t][e] = 0.f;

    const int krow4 = (lane & 7) + ((lane >> 4) << 3);
    const int kko4  = ((lane >> 3) & 1) * 16;       // bytes
#pragma unroll
    for (int u = 0; u < 9; u++) {
        int ntb = 2 * w + 2 * u;
        uint32_t kb_addr = sb + A_K + (uint32_t)(ntb * 8 + krow4) * APITCHB + (uint32_t)kko4;
#pragma unroll
        for (int kc = 0; kc < 4; kc++) {
            uint32_t k4[4];
            ldsm_x4(k4, kb_addr + (uint32_t)kc * 32);
            uint32_t b0[2] = { k4[0], k4[1] }, b1[2] = { k4[2], k4[3] };
            mma_f16(s[2 * u],     qf[kc], b0);
            mma_f16(s[2 * u + 1], qf[kc], b1);
        }
    }

    // ---- mask + softmax ----
    const int g  = lane >> 2;
    const int c2 = (lane & 3) * 2;
    const int qg0 = q0 + w * 16 + g;
    const int qg1 = qg0 + 8;
    const float scale = 0.125f;

    float m0 = -1e30f, m1 = -1e30f;
#pragma unroll
    for (int t = 0; t < 18; t++) {
        int j0 = (2 * w + t) * 8 + c2;
        int kg0 = kbase + j0, kg1 = kg0 + 1;
        bool in0 = (kg0 >= 0) && (kg0 < SEQ);
        bool in1 = (kg1 >= 0) && (kg1 < SEQ);
        int d00 = kg0 - qg0, d10 = kg1 - qg0, d01 = kg0 - qg1, d11 = kg1 - qg1;
        s[t][0] = (in0 && d00 <= WIN && d00 >= -WIN) ? s[t][0] * scale : -1e30f;
        s[t][1] = (in1 && d10 <= WIN && d10 >= -WIN) ? s[t][1] * scale : -1e30f;
        s[t][2] = (in0 && d01 <= WIN && d01 >= -WIN) ? s[t][2] * scale : -1e30f;
        s[t][3] = (in1 && d11 <= WIN && d11 >= -WIN) ? s[t][3] * scale : -1e30f;
        m0 = fmaxf(m0, fmaxf(s[t][0], s[t][1]));
        m1 = fmaxf(m1, fmaxf(s[t][2], s[t][3]));
    }
    m0 = fmaxf(m0, __shfl_xor_sync(0xffffffffu, m0, 1));
    m0 = fmaxf(m0, __shfl_xor_sync(0xffffffffu, m0, 2));
    m1 = fmaxf(m1, __shfl_xor_sync(0xffffffffu, m1, 1));
    m1 = fmaxf(m1, __shfl_xor_sync(0xffffffffu, m1, 2));

    float r0 = 0.f, r1 = 0.f;
#pragma unroll
    for (int t = 0; t < 18; t++) {
        s[t][0] = __expf(s[t][0] - m0);
        s[t][1] = __expf(s[t][1] - m0);
        s[t][2] = __expf(s[t][2] - m1);
        s[t][3] = __expf(s[t][3] - m1);
        r0 += s[t][0] + s[t][1];
        r1 += s[t][2] + s[t][3];
    }
    r0 += __shfl_xor_sync(0xffffffffu, r0, 1);
    r0 += __shfl_xor_sync(0xffffffffu, r0, 2);
    r1 += __shfl_xor_sync(0xffffffffu, r1, 1);
    r1 += __shfl_xor_sync(0xffffffffu, r1, 2);
    float inv0 = 1.f / r0, inv1 = 1.f / r1;

    // ---- pack P into split-fp16 A-fragments (P = ph + pl, near-exact) ----
    uint32_t ph01[18], ph23[18], pl01[18], pl23[18];
#pragma unroll
    for (int t = 0; t < 18; t++) {
        float p0 = s[t][0] * inv0, p1 = s[t][1] * inv0;
        float p2 = s[t][2] * inv1, p3 = s[t][3] * inv1;
        __half2 h2 = __floats2half2_rn(p0, p1);
        ph01[t] = *(uint32_t*)&h2;
        pl01[t] = pack_hf2(p0 - __half2float(h2.x), p1 - __half2float(h2.y));
        h2 = __floats2half2_rn(p2, p3);
        ph23[t] = *(uint32_t*)&h2;
        pl23[t] = pack_hf2(p2 - __half2float(h2.x), p3 - __half2float(h2.y));
    }

    CP_WAIT(0);
    __syncthreads();

    // ---- PV: out[16][64], 2-pass (P hi + P lo), V single fp16 ----
    float o[8][4];
#pragma unroll
    for (int nt = 0; nt < 8; nt++)
#pragma unroll
        for (int e = 0; e < 4; e++) o[nt][e] = 0.f;

    const int vrow_l = ((lane >> 3) & 1) * 8 + (lane & 7);
#pragma unroll
    for (int jl = 0; jl < 9; jl++) {
        uint32_t ah[4] = { ph01[2 * jl], ph23[2 * jl], ph01[2 * jl + 1], ph23[2 * jl + 1] };
        uint32_t al[4] = { pl01[2 * jl], pl23[2 * jl], pl01[2 * jl + 1], pl23[2 * jl + 1] };
        int keyb = (w + jl) * 16;
        uint32_t va_base = sb + A_V + (uint32_t)(keyb + vrow_l) * APITCHB;
#pragma unroll
        for (int nt = 0; nt < 8; nt++) {
            uint32_t vf[2];
            ldsm_x2t(vf, va_base + (uint32_t)nt * 16);
            mma_f16(o[nt], ah, vf);
            mma_f16(o[nt], al, vf);
        }
    }

    size_t row0 = tok0 + qg0;
    size_t row1 = tok0 + qg1;
#pragma unroll
    for (int nt = 0; nt < 8; nt++) {
        int col = coff + nt * 8 + c2;
        *(__half2*)(g_a16 + row0 * DMODEL + col) = __floats2half2_rn(o[nt][0], o[nt][1]);
        *(__half2*)(g_a16 + row1 * DMODEL + col) = __floats2half2_rn(o[nt][2], o[nt][3]);
    }
}

// ============================================================
extern "C" void kernel_launch(void* const* d_in, const int* in_sizes, int n_in,
                              void* d_out, int out_size)
{
    const float* x  = (const float*)d_in[0];
    const float* Wq = (const float*)d_in[1];
    const float* bq = (const float*)d_in[2];
    const float* Wk = (const float*)d_in[3];
    const float* bk = (const float*)d_in[4];
    const float* Wv = (const float*)d_in[5];
    const float* bv = (const float*)d_in[6];
    const float* Wo = (const float*)d_in[7];
    const float* bo = (const float*)d_in[8];
    float* out = (float*)d_out;

    cudaFuncSetAttribute(hmma_gemm_kernel, cudaFuncAttributeMaxDynamicSharedMemorySize, GEMM_SMEM);
    cudaFuncSetAttribute(attn_mma_kernel, cudaFuncAttributeMaxDynamicSharedMemorySize, ATTN_SMEM);

    convert_x_kernel<<<MTOT, 256>>>(x);
    transpose_w_kernel<<<dim3(32, 32, 4), dim3(32, 8)>>>(Wq, Wk, Wv, Wo);

    dim3 gq(DMODEL / 128, MTOT / 128, 3);
    hmma_gemm_kernel<<<gq, 256, GEMM_SMEM>>>(0, bq, bk, bv, nullptr);

    dim3 ga(SEQ / 128, NHEADS, BATCH);
    attn_mma_kernel<<<ga, 256, ATTN_SMEM>>>();

    dim3 go(DMODEL / 128, MTOT / 128, 1);
    hmma_gemm_kernel<<<go, 256, GEMM_SMEM>>>(1, bo, nullptr, nullptr, out);
}

// round 11
// speedup vs baseline: 2.5432x; 1.0933x over previous
#include <cuda_runtime.h>
#include <cuda_bf16.h>
#include <cuda_fp16.h>
#include <math.h>
#include <stdint.h>

#define BATCH   2
#define SEQ     2048
#define DMODEL  1024
#define NHEADS  16
#define HDIM    64
#define WIN     64
#define MTOT    (BATCH*SEQ)   // 4096
#define WSZ     (DMODEL*DMODEL)

// ---------------- scratch (static device globals) ----------------
__device__ __half g_x16[MTOT*DMODEL];          // x rounded to fp16
__device__ __half g_w16[4*WSZ];                // transposed [n][k], fp16
__device__ __half g_q16[MTOT*DMODEL];
__device__ __half g_k16[MTOT*DMODEL];
__device__ __half g_v16[MTOT*DMODEL];
__device__ __half g_a16[MTOT*DMODEL];          // attention out, fp16

// ---------------- PTX helpers (non-'a' features only) ----------------
__device__ __forceinline__ uint32_t smem_u32(const void* p) {
    uint32_t a;
    asm("{ .reg .u64 t; cvta.to.shared.u64 t, %1; cvt.u32.u64 %0, t; }" : "=r"(a) : "l"(p));
    return a;
}
__device__ __forceinline__ void cp_async16(uint32_t s, const void* g) {
    asm volatile("cp.async.cg.shared.global [%0], [%1], 16;" :: "r"(s), "l"(g));
}
__device__ __forceinline__ void cp_async16z(uint32_t s, const void* g, uint32_t srcsz) {
    asm volatile("cp.async.cg.shared.global [%0], [%1], 16, %2;" :: "r"(s), "l"(g), "r"(srcsz));
}
#define CP_COMMIT() asm volatile("cp.async.commit_group;" ::: "memory")
#define CP_WAIT(n)  asm volatile("cp.async.wait_group %0;" :: "n"(n) : "memory")

__device__ __forceinline__ void ldsm_x4(uint32_t* r, uint32_t a) {
    asm volatile("ldmatrix.sync.aligned.m8n8.x4.shared.b16 {%0,%1,%2,%3}, [%4];"
        : "=r"(r[0]), "=r"(r[1]), "=r"(r[2]), "=r"(r[3]) : "r"(a));
}
__device__ __forceinline__ void ldsm_x2t(uint32_t* r, uint32_t a) {
    asm volatile("ldmatrix.sync.aligned.m8n8.x2.trans.shared.b16 {%0,%1}, [%2];"
        : "=r"(r[0]), "=r"(r[1]) : "r"(a));
}
__device__ __forceinline__ void mma_f16(float* d, const uint32_t* a, const uint32_t* b) {
    asm volatile(
        "mma.sync.aligned.m16n8k16.row.col.f32.f16.f16.f32 "
        "{%0,%1,%2,%3}, {%4,%5,%6,%7}, {%8,%9}, {%0,%1,%2,%3};"
        : "+f"(d[0]), "+f"(d[1]), "+f"(d[2]), "+f"(d[3])
        : "r"(a[0]), "r"(a[1]), "r"(a[2]), "r"(a[3]), "r"(b[0]), "r"(b[1]));
}

__device__ __forceinline__ uint32_t pack_hf2(float x, float y) {
    __half2 h = __floats2half2_rn(x, y);
    return *(uint32_t*)&h;
}

// ============================================================
// Fused prep: blocks [0,4096) convert x -> fp16;
//             blocks [4096,8192) transpose W[k][n] -> Wt[n][k] fp16.
// ============================================================
__global__ __launch_bounds__(256) void prep_kernel(
    const float* __restrict__ x,
    const float* __restrict__ Wq, const float* __restrict__ Wk,
    const float* __restrict__ Wv, const float* __restrict__ Wo)
{
    __shared__ float tile[32][33];
    int bid = blockIdx.x;
    if (bid < MTOT) {
        size_t off = (size_t)bid * DMODEL + threadIdx.x * 4;
        float4 v = *(const float4*)(x + off);
        *(__half2*)(g_x16 + off)     = __floats2half2_rn(v.x, v.y);
        *(__half2*)(g_x16 + off + 2) = __floats2half2_rn(v.z, v.w);
    } else {
        int t = bid - MTOT;                 // 0..4095
        int z = t >> 10;                    // 0..3
        int tt = t & 1023;                  // 0..1023
        const float* W = (z == 0) ? Wq : (z == 1) ? Wk : (z == 2) ? Wv : Wo;
        __half* T = g_w16 + (size_t)z * WSZ;
        int kb = (tt >> 5) * 32, nb = (tt & 31) * 32;
        int tx = threadIdx.x & 31, ty = threadIdx.x >> 5;   // ty 0..7
#pragma unroll
        for (int i = 0; i < 4; i++)
            tile[ty + 8 * i][tx] = W[(size_t)(kb + ty + 8 * i) * DMODEL + nb + tx];
        __syncthreads();
#pragma unroll
        for (int i = 0; i < 4; i++) {
            T[(size_t)(nb + ty + 8 * i) * DMODEL + kb + tx] =
                __float2half_rn(tile[tx][ty + 8 * i]);
        }
    }
}

// ============================================================
// Single-pass fp16 HMMA GEMM: C = A16 @ W16^T + bias
// CTA tile 128x128, BK=32, 8 warps (2x4), warp tile 64x32.
// 4-stage cp.async, stage = 20480 B, total 80 KB -> 2 CTAs/SM.
// B fragments via paired ldmatrix.x4 (R6-validated lane mapping).
// ============================================================
#define BK       32
#define PITCHB   80                    // bytes per SMEM row (40 fp16)
#define MAT_B    (128*PITCHB)          // 10240 B per matrix tile
#define STAGE_B2 (2*MAT_B)             // 20480 B per stage
#define NSTAGE   4
#define GEMM_SMEM (NSTAGE*STAGE_B2)    // 81920 B
#define ROW64B   (64*PITCHB)

__global__ __launch_bounds__(256) void hmma_gemm_kernel(
    int mode, const float* __restrict__ b0, const float* __restrict__ b1,
    const float* __restrict__ b2, float* __restrict__ outp)
{
    extern __shared__ char sm[];
    const uint32_t sbase = smem_u32(sm);

    const int tid  = threadIdx.x;
    const int lane = tid & 31;
    const int wid  = tid >> 5;
    const int wm   = wid >> 2;
    const int wn   = wid & 3;
    const int m0   = blockIdx.y * 128;
    const int n0   = blockIdx.x * 128;
    const int z    = blockIdx.z;

    const __half *A, *B;
    const float* bias;
    if (mode == 0) {
        A = g_x16;
        B = g_w16 + (size_t)z * WSZ;
        bias = (z == 0) ? b0 : (z == 1) ? b1 : b2;
    } else {
        A = g_a16;
        B = g_w16 + 3ull * WSZ;
        bias = b0;
    }

    const int rowA = tid >> 2;
    const int seg  = tid & 3;
    const uint32_t s0 = (uint32_t)rowA * PITCHB + (uint32_t)seg * 16;
    const __half* pA = A + (size_t)(m0 + rowA) * DMODEL + seg * 8;
    const __half* pB = B + (size_t)(n0 + rowA) * DMODEL + seg * 8;

#define PREFETCH(stage, cc) do {                                             \
    const int _k0 = (cc) * BK;                                               \
    const uint32_t _sb = sbase + (uint32_t)(stage) * STAGE_B2 + s0;          \
    cp_async16(_sb,                  pA + _k0);                              \
    cp_async16(_sb + ROW64B,         pA + 64 * DMODEL + _k0);                \
    cp_async16(_sb + MAT_B,          pB + _k0);                              \
    cp_async16(_sb + MAT_B + ROW64B, pB + 64 * DMODEL + _k0);                \
} while (0)

    float acc[4][4][4];
#pragma unroll
    for (int i = 0; i < 4; i++)
#pragma unroll
        for (int j = 0; j < 4; j++)
#pragma unroll
            for (int e = 0; e < 4; e++) acc[i][j][e] = 0.f;

    const int arow_l = ((lane >> 3) & 1) * 8 + (lane & 7);
    const int akoff  = (lane >> 4) * 8;
    // B x4 lane mapping (R6-validated): 16 n-rows, two k-halves per x4
    const int brow4  = (lane & 7) + ((lane >> 4) << 3);
    const int bko4   = ((lane >> 3) & 1) * 16;      // bytes

    PREFETCH(0, 0); CP_COMMIT();
    PREFETCH(1, 1); CP_COMMIT();
    PREFETCH(2, 2); CP_COMMIT();

    const int NCHUNK = DMODEL / BK;   // 32
    for (int c = 0; c < NCHUNK; c++) {
        if (c + 3 < NCHUNK)      { PREFETCH((c + 3) & 3, c + 3); CP_COMMIT(); CP_WAIT(3); }
        else if (c + 3 == NCHUNK){ CP_WAIT(2); }
        else if (c + 2 == NCHUNK){ CP_WAIT(1); }
        else                     { CP_WAIT(0); }
        __syncthreads();

        const uint32_t stb = sbase + (uint32_t)(c & 3) * STAGE_B2;
#pragma unroll
        for (int ks = 0; ks < 2; ks++) {
            uint32_t a[4][4], b4[2][4];
#pragma unroll
            for (int mt = 0; mt < 4; mt++) {
                uint32_t ad = stb + (uint32_t)(wm * 64 + mt * 16 + arow_l) * PITCHB
                                  + (uint32_t)(ks * 16 + akoff) * 2;
                ldsm_x4(a[mt], ad);
            }
#pragma unroll
            for (int np = 0; np < 2; np++) {
                uint32_t bd = stb + MAT_B
                                  + (uint32_t)(wn * 32 + np * 16 + brow4) * PITCHB
                                  + (uint32_t)(ks * 32 + bko4);
                ldsm_x4(b4[np], bd);
            }
#pragma unroll
            for (int mt = 0; mt < 4; mt++)
#pragma unroll
                for (int nt = 0; nt < 4; nt++) {
                    uint32_t bfr[2] = { b4[nt >> 1][(nt & 1) * 2 + 0],
                                        b4[nt >> 1][(nt & 1) * 2 + 1] };
                    mma_f16(acc[mt][nt], a[mt], bfr);
                }
        }
        __syncthreads();
    }

    const int g     = lane >> 2;
    const int cpair = (lane & 3) * 2;
    if (mode == 0) {
        __half* C16 = (z == 0) ? g_q16 : (z == 1) ? g_k16 : g_v16;
#pragma unroll
        for (int mt = 0; mt < 4; mt++) {
            int row0 = m0 + wm * 64 + mt * 16 + g;
#pragma unroll
            for (int nt = 0; nt < 4; nt++) {
                int col = n0 + wn * 32 + nt * 8 + cpair;
                float bx = bias[col], by = bias[col + 1];
#pragma unroll
                for (int rr = 0; rr < 2; rr++) {
                    size_t off = (size_t)(row0 + rr * 8) * DMODEL + col;
                    *(__half2*)(C16 + off) =
                        __floats2half2_rn(acc[mt][nt][rr * 2 + 0] + bx,
                                          acc[mt][nt][rr * 2 + 1] + by);
                }
            }
        }
    } else {
        float* C = outp;
#pragma unroll
        for (int mt = 0; mt < 4; mt++) {
            int row0 = m0 + wm * 64 + mt * 16 + g;
#pragma unroll
            for (int nt = 0; nt < 4; nt++) {
                int col = n0 + wn * 32 + nt * 8 + cpair;
                float bx = bias[col], by = bias[col + 1];
                *(float2*)(C + (size_t)row0 * DMODEL + col) =
                    make_float2(acc[mt][nt][0] + bx, acc[mt][nt][1] + by);
                *(float2*)(C + (size_t)(row0 + 8) * DMODEL + col) =
                    make_float2(acc[mt][nt][2] + bx, acc[mt][nt][3] + by);
            }
        }
    }
#undef PREFETCH
}

// ============================================================
// Banded flash-attention, single fp16 Q/K/V, split-fp16 P.
// CTA = (128 queries, head, batch); 8 warps; warp = 16 query rows.
// smem: Q 128x72h, K 256x72h, V 256x72h = 92160 B -> 2 CTAs/SM.
// ============================================================
#define APITCHB  144
#define A_Q      0
#define A_K      18432              // 128*144
#define A_V      55296              // +256*144
#define ATTN_SMEM 92160

__global__ __launch_bounds__(256, 2) void attn_mma_kernel()
{
    extern __shared__ char sm[];
    const uint32_t sb = smem_u32(sm);

    const int tid  = threadIdx.x;
    const int lane = tid & 31;
    const int w    = tid >> 5;          // 0..7
    const int b    = blockIdx.z;
    const int h    = blockIdx.y;
    const int q0   = blockIdx.x * 128;
    const int kbase = q0 - WIN;
    const size_t tok0 = (size_t)b * SEQ;
    const int coff = h * HDIM;

    // ---- group 0: Q (128 rows) + K (256 rows); group 1: V (256 rows) ----
#pragma unroll
    for (int i = 0; i < 4; i++) {
        int task = tid + i * 256;          // 1024 tasks
        int row = task >> 3, seg = task & 7;
        uint32_t d = sb + A_Q + (uint32_t)row * APITCHB + (uint32_t)seg * 16;
        cp_async16(d, g_q16 + (tok0 + q0 + row) * DMODEL + coff + seg * 8);
    }
#pragma unroll
    for (int i = 0; i < 8; i++) {
        int task = tid + i * 256;          // 2048 tasks
        int row = task >> 3, seg = task & 7;
        int kg = kbase + row;
        int kgc = min(max(kg, 0), SEQ - 1);
        uint32_t sz = (kg >= 0 && kg < SEQ) ? 16u : 0u;
        uint32_t d = sb + A_K + (uint32_t)row * APITCHB + (uint32_t)seg * 16;
        cp_async16z(d, g_k16 + (tok0 + kgc) * DMODEL + coff + seg * 8, sz);
    }
    CP_COMMIT();
#pragma unroll
    for (int i = 0; i < 8; i++) {
        int task = tid + i * 256;
        int row = task >> 3, seg = task & 7;
        int kg = kbase + row;
        int kgc = min(max(kg, 0), SEQ - 1);
        uint32_t sz = (kg >= 0 && kg < SEQ) ? 16u : 0u;
        uint32_t d = sb + A_V + (uint32_t)row * APITCHB + (uint32_t)seg * 16;
        cp_async16z(d, g_v16 + (tok0 + kgc) * DMODEL + coff + seg * 8, sz);
    }
    CP_COMMIT();

    CP_WAIT(1);
    __syncthreads();

    // ---- Q fragments ----
    const int arow = w * 16 + ((lane >> 3) & 1) * 8 + (lane & 7);
    const int akoff = (lane >> 4) * 8;
    uint32_t qf[4][4];
#pragma unroll
    for (int kc = 0; kc < 4; kc++) {
        uint32_t ad = sb + A_Q + (uint32_t)arow * APITCHB + (uint32_t)(kc * 16 + akoff) * 2;
        ldsm_x4(qf[kc], ad);
    }

    // ---- QK: S[16][144], 18 n-tiles as 9 pairs via ldsm_x4, 1 pass ----
    float s[18][4];
#pragma unroll
    for (int t = 0; t < 18; t++)
#pragma unroll
        for (int e = 0; e < 4; e++) s[t][e] = 0.f;

    const int krow4 = (lane & 7) + ((lane >> 4) << 3);
    const int kko4  = ((lane >> 3) & 1) * 16;       // bytes
#pragma unroll
    for (int u = 0; u < 9; u++) {
        int ntb = 2 * w + 2 * u;
        uint32_t kb_addr = sb + A_K + (uint32_t)(ntb * 8 + krow4) * APITCHB + (uint32_t)kko4;
#pragma unroll
        for (int kc = 0; kc < 4; kc++) {
            uint32_t k4[4];
            ldsm_x4(k4, kb_addr + (uint32_t)kc * 32);
            uint32_t b0[2] = { k4[0], k4[1] }, b1[2] = { k4[2], k4[3] };
            mma_f16(s[2 * u],     qf[kc], b0);
            mma_f16(s[2 * u + 1], qf[kc], b1);
        }
    }

    // ---- mask + softmax ----
    const int g  = lane >> 2;
    const int c2 = (lane & 3) * 2;
    const int qg0 = q0 + w * 16 + g;
    const int qg1 = qg0 + 8;
    const float scale = 0.125f;

    float m0 = -1e30f, m1 = -1e30f;
#pragma unroll
    for (int t = 0; t < 18; t++) {
        int j0 = (2 * w + t) * 8 + c2;
        int kg0 = kbase + j0, kg1 = kg0 + 1;
        bool in0 = (kg0 >= 0) && (kg0 < SEQ);
        bool in1 = (kg1 >= 0) && (kg1 < SEQ);
        int d00 = kg0 - qg0, d10 = kg1 - qg0, d01 = kg0 - qg1, d11 = kg1 - qg1;
        s[t][0] = (in0 && d00 <= WIN && d00 >= -WIN) ? s[t][0] * scale : -1e30f;
        s[t][1] = (in1 && d10 <= WIN && d10 >= -WIN) ? s[t][1] * scale : -1e30f;
        s[t][2] = (in0 && d01 <= WIN && d01 >= -WIN) ? s[t][2] * scale : -1e30f;
        s[t][3] = (in1 && d11 <= WIN && d11 >= -WIN) ? s[t][3] * scale : -1e30f;
        m0 = fmaxf(m0, fmaxf(s[t][0], s[t][1]));
        m1 = fmaxf(m1, fmaxf(s[t][2], s[t][3]));
    }
    m0 = fmaxf(m0, __shfl_xor_sync(0xffffffffu, m0, 1));
    m0 = fmaxf(m0, __shfl_xor_sync(0xffffffffu, m0, 2));
    m1 = fmaxf(m1, __shfl_xor_sync(0xffffffffu, m1, 1));
    m1 = fmaxf(m1, __shfl_xor_sync(0xffffffffu, m1, 2));

    float r0 = 0.f, r1 = 0.f;
#pragma unroll
    for (int t = 0; t < 18; t++) {
        s[t][0] = __expf(s[t][0] - m0);
        s[t][1] = __expf(s[t][1] - m0);
        s[t][2] = __expf(s[t][2] - m1);
        s[t][3] = __expf(s[t][3] - m1);
        r0 += s[t][0] + s[t][1];
        r1 += s[t][2] + s[t][3];
    }
    r0 += __shfl_xor_sync(0xffffffffu, r0, 1);
    r0 += __shfl_xor_sync(0xffffffffu, r0, 2);
    r1 += __shfl_xor_sync(0xffffffffu, r1, 1);
    r1 += __shfl_xor_sync(0xffffffffu, r1, 2);
    float inv0 = 1.f / r0, inv1 = 1.f / r1;

    // ---- pack P into split-fp16 A-fragments (P = ph + pl, near-exact) ----
    uint32_t ph01[18], ph23[18], pl01[18], pl23[18];
#pragma unroll
    for (int t = 0; t < 18; t++) {
        float p0 = s[t][0] * inv0, p1 = s[t][1] * inv0;
        float p2 = s[t][2] * inv1, p3 = s[t][3] * inv1;
        __half2 h2 = __floats2half2_rn(p0, p1);
        ph01[t] = *(uint32_t*)&h2;
        pl01[t] = pack_hf2(p0 - __half2float(h2.x), p1 - __half2float(h2.y));
        h2 = __floats2half2_rn(p2, p3);
        ph23[t] = *(uint32_t*)&h2;
        pl23[t] = pack_hf2(p2 - __half2float(h2.x), p3 - __half2float(h2.y));
    }

    CP_WAIT(0);
    __syncthreads();

    // ---- PV: out[16][64], 2-pass (P hi + P lo), V single fp16 ----
    float o[8][4];
#pragma unroll
    for (int nt = 0; nt < 8; nt++)
#pragma unroll
        for (int e = 0; e < 4; e++) o[nt][e] = 0.f;

    const int vrow_l = ((lane >> 3) & 1) * 8 + (lane & 7);
#pragma unroll
    for (int jl = 0; jl < 9; jl++) {
        uint32_t ah[4] = { ph01[2 * jl], ph23[2 * jl], ph01[2 * jl + 1], ph23[2 * jl + 1] };
        uint32_t al[4] = { pl01[2 * jl], pl23[2 * jl], pl01[2 * jl + 1], pl23[2 * jl + 1] };
        int keyb = (w + jl) * 16;
        uint32_t va_base = sb + A_V + (uint32_t)(keyb + vrow_l) * APITCHB;
#pragma unroll
        for (int nt = 0; nt < 8; nt++) {
            uint32_t vf[2];
            ldsm_x2t(vf, va_base + (uint32_t)nt * 16);
            mma_f16(o[nt], ah, vf);
            mma_f16(o[nt], al, vf);
        }
    }

    size_t row0 = tok0 + qg0;
    size_t row1 = tok0 + qg1;
#pragma unroll
    for (int nt = 0; nt < 8; nt++) {
        int col = coff + nt * 8 + c2;
        *(__half2*)(g_a16 + row0 * DMODEL + col) = __floats2half2_rn(o[nt][0], o[nt][1]);
        *(__half2*)(g_a16 + row1 * DMODEL + col) = __floats2half2_rn(o[nt][2], o[nt][3]);
    }
}

// ============================================================
extern "C" void kernel_launch(void* const* d_in, const int* in_sizes, int n_in,
                              void* d_out, int out_size)
{
    const float* x  = (const float*)d_in[0];
    const float* Wq = (const float*)d_in[1];
    const float* bq = (const float*)d_in[2];
    const float* Wk = (const float*)d_in[3];
    const float* bk = (const float*)d_in[4];
    const float* Wv = (const float*)d_in[5];
    const float* bv = (const float*)d_in[6];
    const float* Wo = (const float*)d_in[7];
    const float* bo = (const float*)d_in[8];
    float* out = (float*)d_out;

    cudaFuncSetAttribute(hmma_gemm_kernel, cudaFuncAttributeMaxDynamicSharedMemorySize, GEMM_SMEM);
    cudaFuncSetAttribute(attn_mma_kernel, cudaFuncAttributeMaxDynamicSharedMemorySize, ATTN_SMEM);

    prep_kernel<<<MTOT + 4096, 256>>>(x, Wq, Wk, Wv, Wo);

    dim3 gq(DMODEL / 128, MTOT / 128, 3);
    hmma_gemm_kernel<<<gq, 256, GEMM_SMEM>>>(0, bq, bk, bv, nullptr);

    dim3 ga(SEQ / 128, NHEADS, BATCH);
    attn_mma_kernel<<<ga, 256, ATTN_SMEM>>>();

    dim3 go(DMODEL / 128, MTOT / 128, 1);
    hmma_gemm_kernel<<<go, 256, GEMM_SMEM>>>(1, bo, nullptr, nullptr, out);
}

// round 12
// speedup vs baseline: 2.8227x; 1.1099x over previous
#include <cuda_runtime.h>
#include <cuda_bf16.h>
#include <cuda_fp16.h>
#include <math.h>
#include <stdint.h>

#define BATCH   2
#define SEQ     2048
#define DMODEL  1024
#define NHEADS  16
#define HDIM    64
#define WIN     64
#define MTOT    (BATCH*SEQ)   // 4096
#define WSZ     (DMODEL*DMODEL)

// ---------------- scratch (static device globals) ----------------
__device__ __half g_x16[MTOT*DMODEL];          // x rounded to fp16
__device__ __half g_w16[4*WSZ];                // transposed [n][k], fp16
__device__ __half g_q16[MTOT*DMODEL];
__device__ __half g_k16[MTOT*DMODEL];
__device__ __half g_v16[MTOT*DMODEL];
__device__ __half g_a16[MTOT*DMODEL];          // attention out, fp16

// ---------------- PTX helpers (non-'a' features only) ----------------
__device__ __forceinline__ uint32_t smem_u32(const void* p) {
    uint32_t a;
    asm("{ .reg .u64 t; cvta.to.shared.u64 t, %1; cvt.u32.u64 %0, t; }" : "=r"(a) : "l"(p));
    return a;
}
__device__ __forceinline__ void cp_async16(uint32_t s, const void* g) {
    asm volatile("cp.async.cg.shared.global [%0], [%1], 16;" :: "r"(s), "l"(g));
}
__device__ __forceinline__ void cp_async16z(uint32_t s, const void* g, uint32_t srcsz) {
    asm volatile("cp.async.cg.shared.global [%0], [%1], 16, %2;" :: "r"(s), "l"(g), "r"(srcsz));
}
#define CP_COMMIT() asm volatile("cp.async.commit_group;" ::: "memory")
#define CP_WAIT(n)  asm volatile("cp.async.wait_group %0;" :: "n"(n) : "memory")

__device__ __forceinline__ void ldsm_x4(uint32_t* r, uint32_t a) {
    asm volatile("ldmatrix.sync.aligned.m8n8.x4.shared.b16 {%0,%1,%2,%3}, [%4];"
        : "=r"(r[0]), "=r"(r[1]), "=r"(r[2]), "=r"(r[3]) : "r"(a));
}
__device__ __forceinline__ void ldsm_x2t(uint32_t* r, uint32_t a) {
    asm volatile("ldmatrix.sync.aligned.m8n8.x2.trans.shared.b16 {%0,%1}, [%2];"
        : "=r"(r[0]), "=r"(r[1]) : "r"(a));
}
__device__ __forceinline__ void mma_f16(float* d, const uint32_t* a, const uint32_t* b) {
    asm volatile(
        "mma.sync.aligned.m16n8k16.row.col.f32.f16.f16.f32 "
        "{%0,%1,%2,%3}, {%4,%5,%6,%7}, {%8,%9}, {%0,%1,%2,%3};"
        : "+f"(d[0]), "+f"(d[1]), "+f"(d[2]), "+f"(d[3])
        : "r"(a[0]), "r"(a[1]), "r"(a[2]), "r"(a[3]), "r"(b[0]), "r"(b[1]));
}

__device__ __forceinline__ uint32_t pack_hf2(float x, float y) {
    __half2 h = __floats2half2_rn(x, y);
    return *(uint32_t*)&h;
}

// ============================================================
// Fused prep: blocks [0,4096) convert x -> fp16;
//             blocks [4096,8192) transpose W[k][n] -> Wt[n][k] fp16.
// ============================================================
__global__ __launch_bounds__(256) void prep_kernel(
    const float* __restrict__ x,
    const float* __restrict__ Wq, const float* __restrict__ Wk,
    const float* __restrict__ Wv, const float* __restrict__ Wo)
{
    __shared__ float tile[32][33];
    int bid = blockIdx.x;
    if (bid < MTOT) {
        size_t off = (size_t)bid * DMODEL + threadIdx.x * 4;
        float4 v = *(const float4*)(x + off);
        *(__half2*)(g_x16 + off)     = __floats2half2_rn(v.x, v.y);
        *(__half2*)(g_x16 + off + 2) = __floats2half2_rn(v.z, v.w);
    } else {
        int t = bid - MTOT;                 // 0..4095
        int z = t >> 10;                    // 0..3
        int tt = t & 1023;                  // 0..1023
        const float* W = (z == 0) ? Wq : (z == 1) ? Wk : (z == 2) ? Wv : Wo;
        __half* T = g_w16 + (size_t)z * WSZ;
        int kb = (tt >> 5) * 32, nb = (tt & 31) * 32;
        int tx = threadIdx.x & 31, ty = threadIdx.x >> 5;   // ty 0..7
#pragma unroll
        for (int i = 0; i < 4; i++)
            tile[ty + 8 * i][tx] = W[(size_t)(kb + ty + 8 * i) * DMODEL + nb + tx];
        __syncthreads();
#pragma unroll
        for (int i = 0; i < 4; i++) {
            T[(size_t)(nb + ty + 8 * i) * DMODEL + kb + tx] =
                __float2half_rn(tile[tx][ty + 8 * i]);
        }
    }
}

// ============================================================
// Single-pass fp16 HMMA GEMM: C = A16 @ W16^T + bias
// CTA tile 128x128, BK=32, 8 warps (2x4), warp tile 64x32.
// 4-stage cp.async, single __syncthreads per chunk
// (wait -> sync -> compute -> prefetch(c+3)); 80 KB -> 2 CTAs/SM.
// ============================================================
#define BK       32
#define PITCHB   80                    // bytes per SMEM row (40 fp16)
#define MAT_B    (128*PITCHB)          // 10240 B per matrix tile
#define STAGE_B2 (2*MAT_B)             // 20480 B per stage
#define NSTAGE   4
#define GEMM_SMEM (NSTAGE*STAGE_B2)    // 81920 B
#define ROW64B   (64*PITCHB)

__global__ __launch_bounds__(256) void hmma_gemm_kernel(
    int mode, const float* __restrict__ b0, const float* __restrict__ b1,
    const float* __restrict__ b2, float* __restrict__ outp)
{
    extern __shared__ char sm[];
    const uint32_t sbase = smem_u32(sm);

    const int tid  = threadIdx.x;
    const int lane = tid & 31;
    const int wid  = tid >> 5;
    const int wm   = wid >> 2;
    const int wn   = wid & 3;
    const int m0   = blockIdx.y * 128;
    const int n0   = blockIdx.x * 128;
    const int z    = blockIdx.z;

    const __half *A, *B;
    const float* bias;
    if (mode == 0) {
        A = g_x16;
        B = g_w16 + (size_t)z * WSZ;
        bias = (z == 0) ? b0 : (z == 1) ? b1 : b2;
    } else {
        A = g_a16;
        B = g_w16 + 3ull * WSZ;
        bias = b0;
    }

    const int rowA = tid >> 2;
    const int seg  = tid & 3;
    const uint32_t s0 = (uint32_t)rowA * PITCHB + (uint32_t)seg * 16;
    const __half* pA = A + (size_t)(m0 + rowA) * DMODEL + seg * 8;
    const __half* pB = B + (size_t)(n0 + rowA) * DMODEL + seg * 8;

#define PREFETCH(stage, cc) do {                                             \
    const int _k0 = (cc) * BK;                                               \
    const uint32_t _sb = sbase + (uint32_t)(stage) * STAGE_B2 + s0;          \
    cp_async16(_sb,                  pA + _k0);                              \
    cp_async16(_sb + ROW64B,         pA + 64 * DMODEL + _k0);                \
    cp_async16(_sb + MAT_B,          pB + _k0);                              \
    cp_async16(_sb + MAT_B + ROW64B, pB + 64 * DMODEL + _k0);                \
} while (0)

    float acc[4][4][4];
#pragma unroll
    for (int i = 0; i < 4; i++)
#pragma unroll
        for (int j = 0; j < 4; j++)
#pragma unroll
            for (int e = 0; e < 4; e++) acc[i][j][e] = 0.f;

    const int arow_l = ((lane >> 3) & 1) * 8 + (lane & 7);
    const int akoff  = (lane >> 4) * 8;
    // B x4 lane mapping: 16 n-rows, two k-halves per x4
    const int brow4  = (lane & 7) + ((lane >> 4) << 3);
    const int bko4   = ((lane >> 3) & 1) * 16;      // bytes

    PREFETCH(0, 0); CP_COMMIT();
    PREFETCH(1, 1); CP_COMMIT();
    PREFETCH(2, 2); CP_COMMIT();

    const int NCHUNK = DMODEL / BK;   // 32
    for (int c = 0; c < NCHUNK; c++) {
        // Ensure stage c is complete. Outstanding groups at this point:
        // stages c..min(c+2, NCHUNK-1).
        if (c + 3 <= NCHUNK)      { CP_WAIT(2); }
        else if (c + 2 == NCHUNK) { CP_WAIT(1); }
        else                      { CP_WAIT(0); }
        __syncthreads();   // visibility + all warps done reading stage c-1

        const uint32_t stb = sbase + (uint32_t)(c & 3) * STAGE_B2;
#pragma unroll
        for (int ks = 0; ks < 2; ks++) {
            uint32_t a[4][4], b4[2][4];
#pragma unroll
            for (int mt = 0; mt < 4; mt++) {
                uint32_t ad = stb + (uint32_t)(wm * 64 + mt * 16 + arow_l) * PITCHB
                                  + (uint32_t)(ks * 16 + akoff) * 2;
                ldsm_x4(a[mt], ad);
            }
#pragma unroll
            for (int np = 0; np < 2; np++) {
                uint32_t bd = stb + MAT_B
                                  + (uint32_t)(wn * 32 + np * 16 + brow4) * PITCHB
                                  + (uint32_t)(ks * 32 + bko4);
                ldsm_x4(b4[np], bd);
            }
#pragma unroll
            for (int mt = 0; mt < 4; mt++)
#pragma unroll
                for (int nt = 0; nt < 4; nt++) {
                    uint32_t bfr[2] = { b4[nt >> 1][(nt & 1) * 2 + 0],
                                        b4[nt >> 1][(nt & 1) * 2 + 1] };
                    mma_f16(acc[mt][nt], a[mt], bfr);
                }
        }

        // Prefetch stage c+3 into slot (c+3)&3 == (c-1)&3 — safe: the barrier
        // above guarantees every warp finished reading stage c-1.
        if (c + 3 < NCHUNK) { PREFETCH((c + 3) & 3, c + 3); CP_COMMIT(); }
    }

    const int g     = lane >> 2;
    const int cpair = (lane & 3) * 2;
    if (mode == 0) {
        __half* C16 = (z == 0) ? g_q16 : (z == 1) ? g_k16 : g_v16;
#pragma unroll
        for (int mt = 0; mt < 4; mt++) {
            int row0 = m0 + wm * 64 + mt * 16 + g;
#pragma unroll
            for (int nt = 0; nt < 4; nt++) {
                int col = n0 + wn * 32 + nt * 8 + cpair;
                float bx = bias[col], by = bias[col + 1];
#pragma unroll
                for (int rr = 0; rr < 2; rr++) {
                    size_t off = (size_t)(row0 + rr * 8) * DMODEL + col;
                    *(__half2*)(C16 + off) =
                        __floats2half2_rn(acc[mt][nt][rr * 2 + 0] + bx,
                                          acc[mt][nt][rr * 2 + 1] + by);
                }
            }
        }
    } else {
        float* C = outp;
#pragma unroll
        for (int mt = 0; mt < 4; mt++) {
            int row0 = m0 + wm * 64 + mt * 16 + g;
#pragma unroll
            for (int nt = 0; nt < 4; nt++) {
                int col = n0 + wn * 32 + nt * 8 + cpair;
                float bx = bias[col], by = bias[col + 1];
                *(float2*)(C + (size_t)row0 * DMODEL + col) =
                    make_float2(acc[mt][nt][0] + bx, acc[mt][nt][1] + by);
                *(float2*)(C + (size_t)(row0 + 8) * DMODEL + col) =
                    make_float2(acc[mt][nt][2] + bx, acc[mt][nt][3] + by);
            }
        }
    }
#undef PREFETCH
}

// ============================================================
// Banded flash-attention, single fp16 Q/K/V, split-fp16 P.
// CTA = (128 queries, head, batch); 8 warps; warp = 16 query rows.
// smem: Q 128x72h, K 256x72h, V 256x72h = 92160 B -> 2 CTAs/SM.
// ============================================================
#define APITCHB  144
#define A_Q      0
#define A_K      18432              // 128*144
#define A_V      55296              // +256*144
#define ATTN_SMEM 92160

__global__ __launch_bounds__(256, 2) void attn_mma_kernel()
{
    extern __shared__ char sm[];
    const uint32_t sb = smem_u32(sm);

    const int tid  = threadIdx.x;
    const int lane = tid & 31;
    const int w    = tid >> 5;          // 0..7
    const int b    = blockIdx.z;
    const int h    = blockIdx.y;
    const int q0   = blockIdx.x * 128;
    const int kbase = q0 - WIN;
    const size_t tok0 = (size_t)b * SEQ;
    const int coff = h * HDIM;

    // ---- group 0: Q (128 rows) + K (256 rows); group 1: V (256 rows) ----
#pragma unroll
    for (int i = 0; i < 4; i++) {
        int task = tid + i * 256;          // 1024 tasks
        int row = task >> 3, seg = task & 7;
        uint32_t d = sb + A_Q + (uint32_t)row * APITCHB + (uint32_t)seg * 16;
        cp_async16(d, g_q16 + (tok0 + q0 + row) * DMODEL + coff + seg * 8);
    }
#pragma unroll
    for (int i = 0; i < 8; i++) {
        int task = tid + i * 256;          // 2048 tasks
        int row = task >> 3, seg = task & 7;
        int kg = kbase + row;
        int kgc = min(max(kg, 0), SEQ - 1);
        uint32_t sz = (kg >= 0 && kg < SEQ) ? 16u : 0u;
        uint32_t d = sb + A_K + (uint32_t)row * APITCHB + (uint32_t)seg * 16;
        cp_async16z(d, g_k16 + (tok0 + kgc) * DMODEL + coff + seg * 8, sz);
    }
    CP_COMMIT();
#pragma unroll
    for (int i = 0; i < 8; i++) {
        int task = tid + i * 256;
        int row = task >> 3, seg = task & 7;
        int kg = kbase + row;
        int kgc = min(max(kg, 0), SEQ - 1);
        uint32_t sz = (kg >= 0 && kg < SEQ) ? 16u : 0u;
        uint32_t d = sb + A_V + (uint32_t)row * APITCHB + (uint32_t)seg * 16;
        cp_async16z(d, g_v16 + (tok0 + kgc) * DMODEL + coff + seg * 8, sz);
    }
    CP_COMMIT();

    CP_WAIT(1);
    __syncthreads();

    // ---- Q fragments ----
    const int arow = w * 16 + ((lane >> 3) & 1) * 8 + (lane & 7);
    const int akoff = (lane >> 4) * 8;
    uint32_t qf[4][4];
#pragma unroll
    for (int kc = 0; kc < 4; kc++) {
        uint32_t ad = sb + A_Q + (uint32_t)arow * APITCHB + (uint32_t)(kc * 16 + akoff) * 2;
        ldsm_x4(qf[kc], ad);
    }

    // ---- QK: S[16][144], 18 n-tiles as 9 pairs via ldsm_x4, 1 pass ----
    float s[18][4];
#pragma unroll
    for (int t = 0; t < 18; t++)
#pragma unroll
        for (int e = 0; e < 4; e++) s[t][e] = 0.f;

    const int krow4 = (lane & 7) + ((lane >> 4) << 3);
    const int kko4  = ((lane >> 3) & 1) * 16;       // bytes
#pragma unroll
    for (int u = 0; u < 9; u++) {
        int ntb = 2 * w + 2 * u;
        uint32_t kb_addr = sb + A_K + (uint32_t)(ntb * 8 + krow4) * APITCHB + (uint32_t)kko4;
#pragma unroll
        for (int kc = 0; kc < 4; kc++) {
            uint32_t k4[4];
            ldsm_x4(k4, kb_addr + (uint32_t)kc * 32);
            uint32_t b0[2] = { k4[0], k4[1] }, b1[2] = { k4[2], k4[3] };
            mma_f16(s[2 * u],     qf[kc], b0);
            mma_f16(s[2 * u + 1], qf[kc], b1);
        }
    }

    // ---- mask + softmax ----
    const int g  = lane >> 2;
    const int c2 = (lane & 3) * 2;
    const int qg0 = q0 + w * 16 + g;
    const int qg1 = qg0 + 8;
    const float scale = 0.125f;

    float m0 = -1e30f, m1 = -1e30f;
#pragma unroll
    for (int t = 0; t < 18; t++) {
        int j0 = (2 * w + t) * 8 + c2;
        int kg0 = kbase + j0, kg1 = kg0 + 1;
        bool in0 = (kg0 >= 0) && (kg0 < SEQ);
        bool in1 = (kg1 >= 0) && (kg1 < SEQ);
        int d00 = kg0 - qg0, d10 = kg1 - qg0, d01 = kg0 - qg1, d11 = kg1 - qg1;
        s[t][0] = (in0 && d00 <= WIN && d00 >= -WIN) ? s[t][0] * scale : -1e30f;
        s[t][1] = (in1 && d10 <= WIN && d10 >= -WIN) ? s[t][1] * scale : -1e30f;
        s[t][2] = (in0 && d01 <= WIN && d01 >= -WIN) ? s[t][2] * scale : -1e30f;
        s[t][3] = (in1 && d11 <= WIN && d11 >= -WIN) ? s[t][3] * scale : -1e30f;
        m0 = fmaxf(m0, fmaxf(s[t][0], s[t][1]));
        m1 = fmaxf(m1, fmaxf(s[t][2], s[t][3]));
    }
    m0 = fmaxf(m0, __shfl_xor_sync(0xffffffffu, m0, 1));
    m0 = fmaxf(m0, __shfl_xor_sync(0xffffffffu, m0, 2));
    m1 = fmaxf(m1, __shfl_xor_sync(0xffffffffu, m1, 1));
    m1 = fmaxf(m1, __shfl_xor_sync(0xffffffffu, m1, 2));

    float r0 = 0.f, r1 = 0.f;
#pragma unroll
    for (int t = 0; t < 18; t++) {
        s[t][0] = __expf(s[t][0] - m0);
        s[t][1] = __expf(s[t][1] - m0);
        s[t][2] = __expf(s[t][2] - m1);
        s[t][3] = __expf(s[t][3] - m1);
        r0 += s[t][0] + s[t][1];
        r1 += s[t][2] + s[t][3];
    }
    r0 += __shfl_xor_sync(0xffffffffu, r0, 1);
    r0 += __shfl_xor_sync(0xffffffffu, r0, 2);
    r1 += __shfl_xor_sync(0xffffffffu, r1, 1);
    r1 += __shfl_xor_sync(0xffffffffu, r1, 2);
    float inv0 = 1.f / r0, inv1 = 1.f / r1;

    // ---- pack P into split-fp16 A-fragments (P = ph + pl, near-exact) ----
    uint32_t ph01[18], ph23[18], pl01[18], pl23[18];
#pragma unroll
    for (int t = 0; t < 18; t++) {
        float p0 = s[t][0] * inv0, p1 = s[t][1] * inv0;
        float p2 = s[t][2] * inv1, p3 = s[t][3] * inv1;
        __half2 h2 = __floats2half2_rn(p0, p1);
        ph01[t] = *(uint32_t*)&h2;
        pl01[t] = pack_hf2(p0 - __half2float(h2.x), p1 - __half2float(h2.y));
        h2 = __floats2half2_rn(p2, p3);
        ph23[t] = *(uint32_t*)&h2;
        pl23[t] = pack_hf2(p2 - __half2float(h2.x), p3 - __half2float(h2.y));
    }

    CP_WAIT(0);
    __syncthreads();

    // ---- PV: out[16][64], 2-pass (P hi + P lo), V single fp16 ----
    float o[8][4];
#pragma unroll
    for (int nt = 0; nt < 8; nt++)
#pragma unroll
        for (int e = 0; e < 4; e++) o[nt][e] = 0.f;

    const int vrow_l = ((lane >> 3) & 1) * 8 + (lane & 7);
#pragma unroll
    for (int jl = 0; jl < 9; jl++) {
        uint32_t ah[4] = { ph01[2 * jl], ph23[2 * jl], ph01[2 * jl + 1], ph23[2 * jl + 1] };
        uint32_t al[4] = { pl01[2 * jl], pl23[2 * jl], pl01[2 * jl + 1], pl23[2 * jl + 1] };
        int keyb = (w + jl) * 16;
        uint32_t va_base = sb + A_V + (uint32_t)(keyb + vrow_l) * APITCHB;
#pragma unroll
        for (int nt = 0; nt < 8; nt++) {
            uint32_t vf[2];
            ldsm_x2t(vf, va_base + (uint32_t)nt * 16);
            mma_f16(o[nt], ah, vf);
            mma_f16(o[nt], al, vf);
        }
    }

    size_t row0 = tok0 + qg0;
    size_t row1 = tok0 + qg1;
#pragma unroll
    for (int nt = 0; nt < 8; nt++) {
        int col = coff + nt * 8 + c2;
        *(__half2*)(g_a16 + row0 * DMODEL + col) = __floats2half2_rn(o[nt][0], o[nt][1]);
        *(__half2*)(g_a16 + row1 * DMODEL + col) = __floats2half2_rn(o[nt][2], o[nt][3]);
    }
}

// ============================================================
extern "C" void kernel_launch(void* const* d_in, const int* in_sizes, int n_in,
                              void* d_out, int out_size)
{
    const float* x  = (const float*)d_in[0];
    const float* Wq = (const float*)d_in[1];
    const float* bq = (const float*)d_in[2];
    const float* Wk = (const float*)d_in[3];
    const float* bk = (const float*)d_in[4];
    const float* Wv = (const float*)d_in[5];
    const float* bv = (const float*)d_in[6];
    const float* Wo = (const float*)d_in[7];
    const float* bo = (const float*)d_in[8];
    float* out = (float*)d_out;

    cudaFuncSetAttribute(hmma_gemm_kernel, cudaFuncAttributeMaxDynamicSharedMemorySize, GEMM_SMEM);
    cudaFuncSetAttribute(attn_mma_kernel, cudaFuncAttributeMaxDynamicSharedMemorySize, ATTN_SMEM);

    prep_kernel<<<MTOT + 4096, 256>>>(x, Wq, Wk, Wv, Wo);

    dim3 gq(DMODEL / 128, MTOT / 128, 3);
    hmma_gemm_kernel<<<gq, 256, GEMM_SMEM>>>(0, bq, bk, bv, nullptr);

    dim3 ga(SEQ / 128, NHEADS, BATCH);
    attn_mma_kernel<<<ga, 256, ATTN_SMEM>>>();

    dim3 go(DMODEL / 128, MTOT / 128, 1);
    hmma_gemm_kernel<<<go, 256, GEMM_SMEM>>>(1, bo, nullptr, nullptr, out);
}